// round 2
// baseline (speedup 1.0000x reference)
#include <cuda_runtime.h>
#include <cuda_bf16.h>
#include <cstdint>
#include <cstddef>

// Problem constants
#define BATCH 4
#define SEQ   2048
#define EMBED 1024
#define NHEAD 16
#define HDIM  64
#define MROWS (BATCH*SEQ)   // 8192

// ---------------- scratch (static device arrays; no allocation) ----------------
__device__ float g_q[MROWS * EMBED];  // [B,H,T,D]
__device__ float g_k[MROWS * EMBED];  // [B,H,T,D]
__device__ float g_v[MROWS * EMBED];  // [B,H,T,D]
__device__ float g_y[MROWS * EMBED];  // [B,T,C]

// ---------------- SGEMM: C = A @ B^T + bias ----------------
// A: [M,K] row-major (K-contiguous), B: [N,K] row-major (K-contiguous)
// REMAP=true: write to [B,H,T,D] layout (for QKV). false: [M,N] row-major.
#define GBM 128
#define GBN 128
#define GBK 16

template<bool REMAP>
__global__ __launch_bounds__(256)
void sgemm_nt(const float* __restrict__ A, const float* __restrict__ Bm,
              const float* __restrict__ bias, float* __restrict__ C)
{
    const int K = EMBED;
    const int N = EMBED;
    __shared__ float As[GBK][GBM + 4];
    __shared__ float Bs[GBK][GBN + 4];

    int tid = threadIdx.x;
    int tx = tid & 15;          // 0..15 -> 8 cols each
    int ty = tid >> 4;          // 0..15 -> 8 rows each
    int bm = blockIdx.y * GBM;
    int bn = blockIdx.x * GBN;

    float acc[8][8];
    #pragma unroll
    for (int i = 0; i < 8; i++)
        #pragma unroll
        for (int j = 0; j < 8; j++) acc[i][j] = 0.f;

    for (int k0 = 0; k0 < K; k0 += GBK) {
        // load 128x16 A tile and 128x16 B tile (each thread: 2 float4 per tile)
        #pragma unroll
        for (int i = 0; i < 2; i++) {
            int f = tid + i * 256;        // 0..511
            int r = f >> 2;               // 0..127
            int c = (f & 3) * 4;          // 0,4,8,12
            float4 av = *(const float4*)&A[(size_t)(bm + r) * K + k0 + c];
            As[c + 0][r] = av.x; As[c + 1][r] = av.y;
            As[c + 2][r] = av.z; As[c + 3][r] = av.w;
            float4 bv = *(const float4*)&Bm[(size_t)(bn + r) * K + k0 + c];
            Bs[c + 0][r] = bv.x; Bs[c + 1][r] = bv.y;
            Bs[c + 2][r] = bv.z; Bs[c + 3][r] = bv.w;
        }
        __syncthreads();

        #pragma unroll
        for (int k = 0; k < GBK; k++) {
            float a[8], b[8];
            *(float4*)&a[0] = *(float4*)&As[k][ty * 8];
            *(float4*)&a[4] = *(float4*)&As[k][ty * 8 + 4];
            *(float4*)&b[0] = *(float4*)&Bs[k][tx * 8];
            *(float4*)&b[4] = *(float4*)&Bs[k][tx * 8 + 4];
            #pragma unroll
            for (int i = 0; i < 8; i++)
                #pragma unroll
                for (int j = 0; j < 8; j++)
                    acc[i][j] += a[i] * b[j];
        }
        __syncthreads();
    }

    // epilogue: bias + store
    #pragma unroll
    for (int i = 0; i < 8; i++) {
        int m = bm + ty * 8 + i;
        #pragma unroll
        for (int j = 0; j < 8; j += 4) {
            int n = bn + tx * 8 + j;
            float4 bv = *(const float4*)&bias[n];
            float4 v;
            v.x = acc[i][j + 0] + bv.x;
            v.y = acc[i][j + 1] + bv.y;
            v.z = acc[i][j + 2] + bv.z;
            v.w = acc[i][j + 3] + bv.w;
            size_t idx;
            if (REMAP) {
                int b_ = m >> 11;          // m / SEQ
                int t_ = m & (SEQ - 1);
                int h_ = n >> 6;           // n / HDIM
                int d_ = n & (HDIM - 1);
                idx = (((size_t)b_ * NHEAD + h_) * SEQ + t_) * HDIM + d_;
            } else {
                idx = (size_t)m * N + n;
            }
            *(float4*)&C[idx] = v;
        }
    }
}

// ---------------- Flash attention (fp32), 64q x 64k tiles, D=64 ----------------
#define AQ 64
#define AK 64
#define AD 64
#define ASTR 68   // padded stride (keeps 16B alignment, reduces conflicts)

struct AttnSmem {
    float Qt[AD][ASTR];   // [d][q], pre-scaled
    float Kt[AD][ASTR];   // [d][k]
    float Vs[AK][ASTR];   // [k][d]
    float Pt[AK][ASTR];   // [k][q]
    float kmask[AK];      // 0 or -1e30
};

__global__ __launch_bounds__(256)
void attn_kernel(const float* __restrict__ Q, const float* __restrict__ Kv,
                 const float* __restrict__ V, const int* __restrict__ mask,
                 float* __restrict__ Y)
{
    extern __shared__ char smem_raw[];
    AttnSmem& sm = *reinterpret_cast<AttnSmem*>(smem_raw);

    int tid = threadIdx.x;
    int tx = tid & 15;          // key/d cols (4 each)
    int ty = tid >> 4;          // query rows (4 each)
    int bh = blockIdx.y;        // b*NHEAD + h
    int b  = bh >> 4;
    int h  = bh & 15;
    int q0 = blockIdx.x * AQ;

    const float scale = 0.125f;  // 1/sqrt(64)
    const float* Qp = Q + ((size_t)bh * SEQ + q0) * AD;
    const float* Kp = Kv + (size_t)bh * SEQ * AD;
    const float* Vp = V + (size_t)bh * SEQ * AD;
    const int*   mp = mask + (size_t)b * SEQ;

    // load Q tile transposed + pre-scaled
    #pragma unroll
    for (int i = 0; i < 4; i++) {
        int f = tid + i * 256;      // 0..1023
        int r = f >> 4;             // q row 0..63
        int c = (f & 15) * 4;       // d
        float4 v = *(const float4*)&Qp[(size_t)r * AD + c];
        sm.Qt[c + 0][r] = v.x * scale;
        sm.Qt[c + 1][r] = v.y * scale;
        sm.Qt[c + 2][r] = v.z * scale;
        sm.Qt[c + 3][r] = v.w * scale;
    }

    float o[4][4];
    float mrow[4], lrow[4];
    #pragma unroll
    for (int i = 0; i < 4; i++) {
        mrow[i] = -1e30f; lrow[i] = 0.f;
        #pragma unroll
        for (int j = 0; j < 4; j++) o[i][j] = 0.f;
    }
    __syncthreads();

    for (int kt = 0; kt < SEQ; kt += AK) {
        // load K (transposed) and V (natural) tiles
        #pragma unroll
        for (int i = 0; i < 4; i++) {
            int f = tid + i * 256;
            int r = f >> 4;
            int c = (f & 15) * 4;
            float4 kv4 = *(const float4*)&Kp[(size_t)(kt + r) * AD + c];
            sm.Kt[c + 0][r] = kv4.x; sm.Kt[c + 1][r] = kv4.y;
            sm.Kt[c + 2][r] = kv4.z; sm.Kt[c + 3][r] = kv4.w;
            float4 vv4 = *(const float4*)&Vp[(size_t)(kt + r) * AD + c];
            *(float4*)&sm.Vs[r][c] = vv4;
        }
        if (tid < AK) sm.kmask[tid] = (mp[kt + tid] != 0) ? -1e30f : 0.0f;
        __syncthreads();

        // S = Q K^T  (4x4 per thread)
        float s[4][4];
        #pragma unroll
        for (int i = 0; i < 4; i++)
            #pragma unroll
            for (int j = 0; j < 4; j++) s[i][j] = 0.f;

        #pragma unroll
        for (int d = 0; d < AD; d++) {
            float a[4], bb[4];
            *(float4*)a  = *(float4*)&sm.Qt[d][ty * 4];
            *(float4*)bb = *(float4*)&sm.Kt[d][tx * 4];
            #pragma unroll
            for (int i = 0; i < 4; i++)
                #pragma unroll
                for (int j = 0; j < 4; j++)
                    s[i][j] += a[i] * bb[j];
        }
        // mask (per key column)
        #pragma unroll
        for (int j = 0; j < 4; j++) {
            float madd = sm.kmask[tx * 4 + j];
            #pragma unroll
            for (int i = 0; i < 4; i++) s[i][j] += madd;
        }

        // online softmax update (row reductions across the 16 tx lanes)
        #pragma unroll
        for (int i = 0; i < 4; i++) {
            float mx = fmaxf(fmaxf(s[i][0], s[i][1]), fmaxf(s[i][2], s[i][3]));
            #pragma unroll
            for (int w = 1; w < 16; w <<= 1)
                mx = fmaxf(mx, __shfl_xor_sync(0xffffffffu, mx, w));
            float mnew = fmaxf(mrow[i], mx);
            float alpha = __expf(mrow[i] - mnew);
            mrow[i] = mnew;
            float rs = 0.f;
            #pragma unroll
            for (int j = 0; j < 4; j++) {
                s[i][j] = __expf(s[i][j] - mnew);
                rs += s[i][j];
            }
            #pragma unroll
            for (int w = 1; w < 16; w <<= 1)
                rs += __shfl_xor_sync(0xffffffffu, rs, w);
            lrow[i] = lrow[i] * alpha + rs;
            #pragma unroll
            for (int j = 0; j < 4; j++) o[i][j] *= alpha;
        }

        // store P transposed: Pt[k][q]
        #pragma unroll
        for (int i = 0; i < 4; i++)
            #pragma unroll
            for (int j = 0; j < 4; j++)
                sm.Pt[tx * 4 + j][ty * 4 + i] = s[i][j];
        __syncthreads();

        // O += P V  (inner over key dim)
        #pragma unroll
        for (int kc = 0; kc < AK; kc++) {
            float a[4], bb[4];
            *(float4*)a  = *(float4*)&sm.Pt[kc][ty * 4];
            *(float4*)bb = *(float4*)&sm.Vs[kc][tx * 4];
            #pragma unroll
            for (int i = 0; i < 4; i++)
                #pragma unroll
                for (int j = 0; j < 4; j++)
                    o[i][j] += a[i] * bb[j];
        }
        __syncthreads();
    }

    // epilogue: normalize, write to [B,T,C] scratch
    #pragma unroll
    for (int i = 0; i < 4; i++) {
        float inv = 1.0f / lrow[i];
        int q = q0 + ty * 4 + i;
        float4 v;
        v.x = o[i][0] * inv; v.y = o[i][1] * inv;
        v.z = o[i][2] * inv; v.w = o[i][3] * inv;
        *(float4*)&Y[((size_t)b * SEQ + q) * EMBED + h * AD + tx * 4] = v;
    }
}

// ---------------- launch ----------------
extern "C" void kernel_launch(void* const* d_in, const int* in_sizes, int n_in,
                              void* d_out, int out_size)
{
    const float* x    = (const float*)d_in[0];
    const int*   mask = (const int*)  d_in[1];
    const float* Wk   = (const float*)d_in[2];
    const float* bk   = (const float*)d_in[3];
    const float* Wq   = (const float*)d_in[4];
    const float* bq   = (const float*)d_in[5];
    const float* Wv   = (const float*)d_in[6];
    const float* bv   = (const float*)d_in[7];
    const float* Wo   = (const float*)d_in[8];
    const float* bo   = (const float*)d_in[9];
    float* out = (float*)d_out;

    float *q, *k, *v, *y;
    cudaGetSymbolAddress((void**)&q, g_q);
    cudaGetSymbolAddress((void**)&k, g_k);
    cudaGetSymbolAddress((void**)&v, g_v);
    cudaGetSymbolAddress((void**)&y, g_y);

    static_assert(sizeof(AttnSmem) <= 160 * 1024, "smem");
    cudaFuncSetAttribute(attn_kernel, cudaFuncAttributeMaxDynamicSharedMemorySize,
                         (int)sizeof(AttnSmem));

    dim3 gblk(EMBED / GBN, MROWS / GBM);   // (8, 64)
    sgemm_nt<true><<<gblk, 256>>>(x, Wq, bq, q);
    sgemm_nt<true><<<gblk, 256>>>(x, Wk, bk, k);
    sgemm_nt<true><<<gblk, 256>>>(x, Wv, bv, v);

    dim3 gattn(SEQ / AQ, BATCH * NHEAD);   // (32, 64)
    attn_kernel<<<gattn, 256, sizeof(AttnSmem)>>>(q, k, v, mask, y);

    sgemm_nt<false><<<gblk, 256>>>(y, Wo, bo, out);
}

// round 3
// speedup vs baseline: 2.7053x; 2.7053x over previous
#include <cuda_runtime.h>
#include <cuda_bf16.h>
#include <cstdint>
#include <cstddef>

// Problem constants
#define BATCH 4
#define SEQ   2048
#define EMBED 1024
#define NHEAD 16
#define HDIM  64
#define MROWS (BATCH*SEQ)   // 8192

// ---------------- scratch (static device arrays; no allocation) ----------------
__device__ float g_q[MROWS * EMBED];  // [B,H,T,D]
__device__ float g_k[MROWS * EMBED];  // [B,H,T,D]
__device__ float g_v[MROWS * EMBED];  // [B,H,T,D]
__device__ float g_y[MROWS * EMBED];  // [B,T,C]

// ---------------- tf32 mma helpers ----------------
__device__ __forceinline__ uint32_t f2tf(float f) {
    uint32_t u;
    asm("cvt.rna.tf32.f32 %0, %1;" : "=r"(u) : "f"(f));
    return u;
}

__device__ __forceinline__ void mma8(float* c,
                                     uint32_t a0, uint32_t a1, uint32_t a2, uint32_t a3,
                                     uint32_t b0, uint32_t b1) {
    asm volatile(
        "mma.sync.aligned.m16n8k8.row.col.f32.tf32.tf32.f32 "
        "{%0,%1,%2,%3}, {%4,%5,%6,%7}, {%8,%9}, {%0,%1,%2,%3};\n"
        : "+f"(c[0]), "+f"(c[1]), "+f"(c[2]), "+f"(c[3])
        : "r"(a0), "r"(a1), "r"(a2), "r"(a3), "r"(b0), "r"(b1));
}

// ---------------- tf32 GEMM: C = A @ B^T + bias ----------------
// A: [M,K] row-major, B: [N,K] row-major. Tile 128x128, k-tile 32.
// 8 warps: warp grid 2x4, warp tile 64x32 (4 m-tiles x 4 n-tiles of m16n8).
// smem stride 36 words: frag access pattern (4*(lane>>2)+(lane&3))%32 -> conflict-free.
template<bool REMAP>
__global__ __launch_bounds__(256)
void gemm_tf32(const float* __restrict__ A, const float* __restrict__ Bm,
               const float* __restrict__ bias, float* __restrict__ C)
{
    const int K = EMBED, N = EMBED;
    __shared__ uint32_t As[128 * 36];
    __shared__ uint32_t Bs[128 * 36];

    int tid = threadIdx.x, lane = tid & 31, w = tid >> 5;
    int wm = (w >> 2) * 64, wn = (w & 3) * 32;
    int bm = blockIdx.y * 128, bn = blockIdx.x * 128;

    float acc[4][4][4] = {};

    for (int k0 = 0; k0 < K; k0 += 32) {
        #pragma unroll
        for (int i = 0; i < 4; i++) {
            int lin = tid + i * 256;         // 0..1023
            int r = lin >> 3;                // 0..127
            int c = (lin & 7) * 4;           // 0..28
            float4 av = *(const float4*)&A[(size_t)(bm + r) * K + k0 + c];
            uint4 at = { f2tf(av.x), f2tf(av.y), f2tf(av.z), f2tf(av.w) };
            *(uint4*)&As[r * 36 + c] = at;
            float4 bv = *(const float4*)&Bm[(size_t)(bn + r) * K + k0 + c];
            uint4 bt = { f2tf(bv.x), f2tf(bv.y), f2tf(bv.z), f2tf(bv.w) };
            *(uint4*)&Bs[r * 36 + c] = bt;
        }
        __syncthreads();

        #pragma unroll
        for (int ks = 0; ks < 4; ks++) {
            uint32_t bfr[4][2];
            #pragma unroll
            for (int nt = 0; nt < 4; nt++) {
                int base = (wn + nt * 8 + (lane >> 2)) * 36 + ks * 8 + (lane & 3);
                bfr[nt][0] = Bs[base];
                bfr[nt][1] = Bs[base + 4];
            }
            #pragma unroll
            for (int mt = 0; mt < 4; mt++) {
                int base = (wm + mt * 16 + (lane >> 2)) * 36 + ks * 8 + (lane & 3);
                uint32_t a0 = As[base],     a1 = As[base + 8 * 36];
                uint32_t a2 = As[base + 4], a3 = As[base + 8 * 36 + 4];
                #pragma unroll
                for (int nt = 0; nt < 4; nt++)
                    mma8(acc[mt][nt], a0, a1, a2, a3, bfr[nt][0], bfr[nt][1]);
            }
        }
        __syncthreads();
    }

    // epilogue: bias + store (c0,c1 = row, cols 2j,2j+1 ; c2,c3 = row+8)
    int jc = 2 * (lane & 3);
    #pragma unroll
    for (int mt = 0; mt < 4; mt++) {
        #pragma unroll
        for (int h = 0; h < 2; h++) {
            int m = bm + wm + mt * 16 + (lane >> 2) + 8 * h;
            #pragma unroll
            for (int nt = 0; nt < 4; nt++) {
                int n = bn + wn + nt * 8 + jc;
                float2 bv = *(const float2*)&bias[n];
                float2 v;
                v.x = acc[mt][nt][2 * h]     + bv.x;
                v.y = acc[mt][nt][2 * h + 1] + bv.y;
                size_t idx;
                if (REMAP) {
                    int b_ = m >> 11, t_ = m & (SEQ - 1);
                    int h_ = n >> 6, d_ = n & 63;
                    idx = (((size_t)b_ * NHEAD + h_) * SEQ + t_) * HDIM + d_;
                } else {
                    idx = (size_t)m * N + n;
                }
                *(float2*)&C[idx] = v;
            }
        }
    }
}

// ---------------- Flash attention with tf32 mma ----------------
// Block: 128 queries, 8 warps (16 q rows each), key tiles of 64, D=64.
#define QBLK 128

struct AttnSmem2 {
    uint32_t Qs[QBLK * 68];   // [q][d], tf32, pre-scaled; stride 68 -> conflict-free A-frags
    uint32_t Ks[64 * 68];     // [k][d], tf32; conflict-free B-frags for S
    uint32_t Vs[64 * 72];     // [k][d], tf32; stride 72 -> conflict-free B-frags for PV
    uint32_t Ps[QBLK * 68];   // [q][k], tf32 probabilities (warp-private rows)
    float kmask[64];          // 0 or -1e30
};

__global__ __launch_bounds__(256)
void attn_tf32(const float* __restrict__ Q, const float* __restrict__ Kv,
               const float* __restrict__ V, const int* __restrict__ mask,
               float* __restrict__ Y)
{
    extern __shared__ char raw[];
    AttnSmem2& sm = *reinterpret_cast<AttnSmem2*>(raw);

    int tid = threadIdx.x, lane = tid & 31, w = tid >> 5;
    int jc = 2 * (lane & 3);
    int bh = blockIdx.y, b = bh >> 4, hh = bh & 15;
    int q0 = blockIdx.x * QBLK;
    int qb = w * 16;                       // warp's q-row base in block

    const float scale = 0.125f;            // 1/sqrt(64)
    const float* Qp = Q + ((size_t)bh * SEQ + q0) * HDIM;
    const float* Kp = Kv + (size_t)bh * SEQ * HDIM;
    const float* Vp = V + (size_t)bh * SEQ * HDIM;
    const int*   mp = mask + (size_t)b * SEQ;

    // load Q tile (128x64), pre-scaled, tf32
    #pragma unroll
    for (int i = 0; i < 8; i++) {
        int lin = tid + i * 256;
        int r = lin >> 4, c = (lin & 15) * 4;
        float4 v = *(const float4*)&Qp[(size_t)r * HDIM + c];
        uint4 t = { f2tf(v.x * scale), f2tf(v.y * scale),
                    f2tf(v.z * scale), f2tf(v.w * scale) };
        *(uint4*)&sm.Qs[r * 68 + c] = t;
    }

    float o[8][4] = {};
    float mrow[2] = { -1e30f, -1e30f };
    float lrow[2] = { 0.f, 0.f };
    __syncthreads();

    for (int kt = 0; kt < SEQ; kt += 64) {
        // stage K, V tiles (64x64 each) + mask
        #pragma unroll
        for (int i = 0; i < 4; i++) {
            int lin = tid + i * 256;
            int r = lin >> 4, c = (lin & 15) * 4;
            float4 kv4 = *(const float4*)&Kp[(size_t)(kt + r) * HDIM + c];
            uint4 t = { f2tf(kv4.x), f2tf(kv4.y), f2tf(kv4.z), f2tf(kv4.w) };
            *(uint4*)&sm.Ks[r * 68 + c] = t;
            float4 vv4 = *(const float4*)&Vp[(size_t)(kt + r) * HDIM + c];
            uint4 t2 = { f2tf(vv4.x), f2tf(vv4.y), f2tf(vv4.z), f2tf(vv4.w) };
            *(uint4*)&sm.Vs[r * 72 + c] = t2;
        }
        if (tid < 64) sm.kmask[tid] = (mp[kt + tid] != 0) ? -1e30f : 0.f;
        __syncthreads();

        // S = Q K^T : 1 m-tile x 8 n-tiles x 8 k-steps per warp
        float s[8][4] = {};
        #pragma unroll
        for (int ks = 0; ks < 8; ks++) {
            int abase = (qb + (lane >> 2)) * 68 + ks * 8 + (lane & 3);
            uint32_t a0 = sm.Qs[abase],     a1 = sm.Qs[abase + 8 * 68];
            uint32_t a2 = sm.Qs[abase + 4], a3 = sm.Qs[abase + 8 * 68 + 4];
            #pragma unroll
            for (int nt = 0; nt < 8; nt++) {
                int bbase = (nt * 8 + (lane >> 2)) * 68 + ks * 8 + (lane & 3);
                mma8(s[nt], a0, a1, a2, a3, sm.Ks[bbase], sm.Ks[bbase + 4]);
            }
        }

        // mask (per key column)
        #pragma unroll
        for (int nt = 0; nt < 8; nt++) {
            float m0 = sm.kmask[nt * 8 + jc];
            float m1 = sm.kmask[nt * 8 + jc + 1];
            s[nt][0] += m0; s[nt][1] += m1;
            s[nt][2] += m0; s[nt][3] += m1;
        }

        // online softmax per half-row (h=0: row=lane>>2 ; h=1: row+8)
        #pragma unroll
        for (int h = 0; h < 2; h++) {
            float mx = -1e30f;
            #pragma unroll
            for (int nt = 0; nt < 8; nt++)
                mx = fmaxf(mx, fmaxf(s[nt][2 * h], s[nt][2 * h + 1]));
            mx = fmaxf(mx, __shfl_xor_sync(0xffffffffu, mx, 1));
            mx = fmaxf(mx, __shfl_xor_sync(0xffffffffu, mx, 2));
            float mnew = fmaxf(mrow[h], mx);
            float alpha = __expf(mrow[h] - mnew);
            mrow[h] = mnew;
            float rs = 0.f;
            #pragma unroll
            for (int nt = 0; nt < 8; nt++) {
                s[nt][2 * h]     = __expf(s[nt][2 * h]     - mnew);
                s[nt][2 * h + 1] = __expf(s[nt][2 * h + 1] - mnew);
                rs += s[nt][2 * h] + s[nt][2 * h + 1];
            }
            rs += __shfl_xor_sync(0xffffffffu, rs, 1);
            rs += __shfl_xor_sync(0xffffffffu, rs, 2);
            lrow[h] = lrow[h] * alpha + rs;
            #pragma unroll
            for (int nt = 0; nt < 8; nt++) {
                o[nt][2 * h]     *= alpha;
                o[nt][2 * h + 1] *= alpha;
            }
        }

        // P (C-frag layout) -> smem (A-frag layout source); warp-private rows
        #pragma unroll
        for (int h = 0; h < 2; h++) {
            int pr = (qb + (lane >> 2) + 8 * h) * 68;
            #pragma unroll
            for (int nt = 0; nt < 8; nt++) {
                sm.Ps[pr + nt * 8 + jc]     = f2tf(s[nt][2 * h]);
                sm.Ps[pr + nt * 8 + jc + 1] = f2tf(s[nt][2 * h + 1]);
            }
        }
        __syncwarp();

        // O += P V : 8 k-steps (key dim) x 8 n-tiles (d)
        #pragma unroll
        for (int ks = 0; ks < 8; ks++) {
            int abase = (qb + (lane >> 2)) * 68 + ks * 8 + (lane & 3);
            uint32_t a0 = sm.Ps[abase],     a1 = sm.Ps[abase + 8 * 68];
            uint32_t a2 = sm.Ps[abase + 4], a3 = sm.Ps[abase + 8 * 68 + 4];
            int kr = ks * 8 + (lane & 3);
            #pragma unroll
            for (int nt = 0; nt < 8; nt++) {
                int bb = kr * 72 + nt * 8 + (lane >> 2);
                mma8(o[nt], a0, a1, a2, a3, sm.Vs[bb], sm.Vs[bb + 4 * 72]);
            }
        }
        __syncthreads();
    }

    // epilogue: normalize, write to [B,T,C]
    #pragma unroll
    for (int h = 0; h < 2; h++) {
        float inv = 1.f / lrow[h];
        int q = q0 + qb + (lane >> 2) + 8 * h;
        #pragma unroll
        for (int nt = 0; nt < 8; nt++) {
            float2 v = { o[nt][2 * h] * inv, o[nt][2 * h + 1] * inv };
            *(float2*)&Y[((size_t)b * SEQ + q) * EMBED + hh * HDIM + nt * 8 + jc] = v;
        }
    }
}

// ---------------- launch ----------------
extern "C" void kernel_launch(void* const* d_in, const int* in_sizes, int n_in,
                              void* d_out, int out_size)
{
    const float* x    = (const float*)d_in[0];
    const int*   mask = (const int*)  d_in[1];
    const float* Wk   = (const float*)d_in[2];
    const float* bk   = (const float*)d_in[3];
    const float* Wq   = (const float*)d_in[4];
    const float* bq   = (const float*)d_in[5];
    const float* Wv   = (const float*)d_in[6];
    const float* bv   = (const float*)d_in[7];
    const float* Wo   = (const float*)d_in[8];
    const float* bo   = (const float*)d_in[9];
    float* out = (float*)d_out;

    float *q, *k, *v, *y;
    cudaGetSymbolAddress((void**)&q, g_q);
    cudaGetSymbolAddress((void**)&k, g_k);
    cudaGetSymbolAddress((void**)&v, g_v);
    cudaGetSymbolAddress((void**)&y, g_y);

    cudaFuncSetAttribute(attn_tf32, cudaFuncAttributeMaxDynamicSharedMemorySize,
                         (int)sizeof(AttnSmem2));

    dim3 gblk(EMBED / 128, MROWS / 128);   // (8, 64)
    gemm_tf32<true><<<gblk, 256>>>(x, Wq, bq, q);
    gemm_tf32<true><<<gblk, 256>>>(x, Wk, bk, k);
    gemm_tf32<true><<<gblk, 256>>>(x, Wv, bv, v);

    dim3 gattn(SEQ / QBLK, BATCH * NHEAD); // (16, 64)
    attn_tf32<<<gattn, 256, sizeof(AttnSmem2)>>>(q, k, v, mask, y);

    gemm_tf32<false><<<gblk, 256>>>(y, Wo, bo, out);
}

// round 5
// speedup vs baseline: 5.5554x; 2.0535x over previous
#include <cuda_runtime.h>
#include <cuda_fp16.h>
#include <cstdint>
#include <cstddef>

// Problem constants
#define BATCH 4
#define SEQ   2048
#define EMBED 1024
#define NHEAD 16
#define HDIM  64
#define MROWS (BATCH*SEQ)   // 8192

// ---------------- scratch (static device arrays; no allocation) ----------------
__device__ __half g_xh[MROWS * EMBED];   // x  fp16 [M,K]
__device__ __half g_wq[EMBED * EMBED];   // W  fp16 [N,K]
__device__ __half g_wk[EMBED * EMBED];
__device__ __half g_wv[EMBED * EMBED];
__device__ __half g_wo[EMBED * EMBED];
__device__ __half g_qh[MROWS * EMBED];   // [B,H,T,D]
__device__ __half g_kh[MROWS * EMBED];   // [B,H,T,D]
__device__ __half g_vt[MROWS * EMBED];   // [B,H,D,T]  (transposed V)
__device__ __half g_yh[MROWS * EMBED];   // [B,T,C]

// ---------------- helpers ----------------
__device__ __forceinline__ uint32_t smem_u32(const void* p) {
    uint32_t a;
    asm("{ .reg .u64 t; cvta.to.shared.u64 t, %1; cvt.u32.u64 %0, t; }" : "=r"(a) : "l"(p));
    return a;
}
__device__ __forceinline__ void cp16(uint32_t dst, const void* src) {
    asm volatile("cp.async.cg.shared.global [%0], [%1], 16;" :: "r"(dst), "l"(src));
}
#define CP_COMMIT() asm volatile("cp.async.commit_group;" ::: "memory")
#define CP_WAIT0()  asm volatile("cp.async.wait_group 0;" ::: "memory")
#define CP_WAIT1()  asm volatile("cp.async.wait_group 1;" ::: "memory")
#define CP_WAIT3()  asm volatile("cp.async.wait_group 3;" ::: "memory")

__device__ __forceinline__ void mma16(float* c,
                                      uint32_t a0, uint32_t a1, uint32_t a2, uint32_t a3,
                                      uint32_t b0, uint32_t b1) {
    asm volatile(
        "mma.sync.aligned.m16n8k16.row.col.f32.f16.f16.f32 "
        "{%0,%1,%2,%3}, {%4,%5,%6,%7}, {%8,%9}, {%0,%1,%2,%3};\n"
        : "+f"(c[0]), "+f"(c[1]), "+f"(c[2]), "+f"(c[3])
        : "r"(a0), "r"(a1), "r"(a2), "r"(a3), "r"(b0), "r"(b1));
}

// ---------------- prep: fp32 -> fp16 ----------------
__global__ void f32_to_f16(const float4* __restrict__ in, uint2* __restrict__ out, int n4) {
    for (int i = blockIdx.x * blockDim.x + threadIdx.x; i < n4; i += gridDim.x * blockDim.x) {
        float4 v = in[i];
        __half2 h01 = __floats2half2_rn(v.x, v.y);
        __half2 h23 = __floats2half2_rn(v.z, v.w);
        uint2 o = { *(uint32_t*)&h01, *(uint32_t*)&h23 };
        out[i] = o;
    }
}

// ---------------- fp16 GEMM: C = A @ B^T + bias ----------------
// A: [M,1024] half, B: [N,1024] half. CTA tile 128x128, k-tile 32, 4-stage cp.async.
// smem rows stride 40 halves (80B) -> conflict-free half2 fragment loads.
// EPI: 0 = half out remapped [B,H,T,D]; 1 = half out transposed [B,H,D,T]; 2 = fp32 [M,N].
#define GSTAGE_B 20480                       // bytes per stage (A 10240 + B 10240)
#define GSMEM_TOTAL (4 * GSTAGE_B)           // 81920

template<int EPI>
__global__ __launch_bounds__(256)
void gemm_h(const __half* __restrict__ A, const __half* __restrict__ Bm,
            const float* __restrict__ bias, void* __restrict__ Cout)
{
    const int K = EMBED;
    extern __shared__ __half sh[];
    uint32_t sbase = smem_u32(sh);

    int tid = threadIdx.x, lane = tid & 31, w = tid >> 5;
    int wm = (w >> 2) * 64, wn = (w & 3) * 32;
    int bm = blockIdx.y * 128, bn = blockIdx.x * 128;

    const __half* Ab = A + (size_t)bm * K;
    const __half* Bb = Bm + (size_t)bn * K;

    auto fill = [&](int st, int kt) {
        uint32_t sA = sbase + st * GSTAGE_B;
        #pragma unroll
        for (int i = 0; i < 2; i++) {
            int ch = tid + i * 256;          // 0..511
            int r = ch >> 2, c = ch & 3;
            cp16(sA + r * 80 + c * 16,         Ab + (size_t)r * K + kt * 32 + c * 8);
            cp16(sA + 10240 + r * 80 + c * 16, Bb + (size_t)r * K + kt * 32 + c * 8);
        }
    };

    float acc[4][4][4] = {};

    #pragma unroll
    for (int p = 0; p < 3; p++) { fill(p, p); CP_COMMIT(); }

    for (int ci = 0; ci < 32; ci++) {
        if (ci + 3 < 32) fill((ci + 3) & 3, ci + 3);
        CP_COMMIT();
        CP_WAIT3();
        __syncthreads();

        const __half* sa = sh + (ci & 3) * (GSTAGE_B / 2);
        const __half* sb = sa + 5120;
        #pragma unroll
        for (int ks = 0; ks < 2; ks++) {
            uint32_t afr[4][4];
            #pragma unroll
            for (int mt = 0; mt < 4; mt++) {
                int row = wm + mt * 16 + (lane >> 2);
                int base = row * 40 + ks * 16 + 2 * (lane & 3);
                afr[mt][0] = *(const uint32_t*)&sa[base];
                afr[mt][1] = *(const uint32_t*)&sa[base + 8 * 40];
                afr[mt][2] = *(const uint32_t*)&sa[base + 8];
                afr[mt][3] = *(const uint32_t*)&sa[base + 8 * 40 + 8];
            }
            #pragma unroll
            for (int nt = 0; nt < 4; nt++) {
                int rn = wn + nt * 8 + (lane >> 2);
                int nb = rn * 40 + ks * 16 + 2 * (lane & 3);
                uint32_t b0 = *(const uint32_t*)&sb[nb];
                uint32_t b1 = *(const uint32_t*)&sb[nb + 8];
                #pragma unroll
                for (int mt = 0; mt < 4; mt++)
                    mma16(acc[mt][nt], afr[mt][0], afr[mt][1], afr[mt][2], afr[mt][3], b0, b1);
            }
        }
        __syncthreads();
    }

    // epilogue
    int jc = 2 * (lane & 3);
    #pragma unroll
    for (int mt = 0; mt < 4; mt++) {
        #pragma unroll
        for (int h = 0; h < 2; h++) {
            int m = bm + wm + mt * 16 + (lane >> 2) + 8 * h;
            #pragma unroll
            for (int nt = 0; nt < 4; nt++) {
                int n = bn + wn + nt * 8 + jc;
                float2 bv = *(const float2*)&bias[n];
                float v0 = acc[mt][nt][2 * h]     + bv.x;
                float v1 = acc[mt][nt][2 * h + 1] + bv.y;
                if (EPI == 0) {
                    int b_ = m >> 11, t_ = m & (SEQ - 1);
                    int h_ = n >> 6, d_ = n & 63;
                    __half2 hv = __floats2half2_rn(v0, v1);
                    *(__half2*)&((__half*)Cout)[(((size_t)b_ * NHEAD + h_) * SEQ + t_) * HDIM + d_] = hv;
                } else if (EPI == 1) {
                    int b_ = m >> 11, t_ = m & (SEQ - 1);
                    int h_ = n >> 6, d_ = n & 63;
                    __half* o = (__half*)Cout;
                    size_t base = ((size_t)b_ * NHEAD + h_) * HDIM;
                    o[(base + d_)     * SEQ + t_] = __float2half_rn(v0);
                    o[(base + d_ + 1) * SEQ + t_] = __float2half_rn(v1);
                } else {
                    float2 v = { v0, v1 };
                    *(float2*)&((float*)Cout)[(size_t)m * EMBED + n] = v;
                }
            }
        }
    }
}

// ---------------- fp16 flash attention ----------------
// 128 queries/CTA, 8 warps x 16 q-rows, key tiles of 64, D=64.
// Strides 72 halves (36 words) -> conflict-free half2 frag access.
struct AttnSmemH {
    __half Qs[128 * 72];      // [q][d]
    __half Ks[2][64 * 72];    // [key][d]   double-buffered
    __half Vt[2][64 * 72];    // [d][key]   double-buffered
    __half Ps[128 * 72];      // [q][key]
    int    mi[2][64];         // mask ints
};

__global__ __launch_bounds__(256)
void attn_h(const __half* __restrict__ Q, const __half* __restrict__ Kh,
            const __half* __restrict__ Vt, const int* __restrict__ mask,
            __half* __restrict__ Y)
{
    extern __shared__ char raw[];
    AttnSmemH& sm = *reinterpret_cast<AttnSmemH*>(raw);

    int tid = threadIdx.x, lane = tid & 31, w = tid >> 5;
    int jc = 2 * (lane & 3);
    int bh = blockIdx.y, b = bh >> 4, hh = bh & 15;
    int q0 = blockIdx.x * 128;
    int qb = w * 16;

    const __half* Qp = Q  + ((size_t)bh * SEQ + q0) * HDIM;
    const __half* Kp = Kh + (size_t)bh * SEQ * HDIM;
    const __half* Vp = Vt + (size_t)bh * HDIM * SEQ;
    const int*    mp = mask + (size_t)b * SEQ;

    uint32_t uQ = smem_u32(sm.Qs);

    // stage Q (128 x 64 halves)
    #pragma unroll
    for (int i = 0; i < 4; i++) {
        int ch = tid + i * 256;          // 0..1023
        int r = ch >> 3, c = ch & 7;
        cp16(uQ + r * 144 + c * 16, Qp + (size_t)r * HDIM + c * 8);
    }

    auto prefetch = [&](int ti, int buf) {
        int kt = ti * 64;
        uint32_t uK = smem_u32(sm.Ks[buf]);
        uint32_t uV = smem_u32(sm.Vt[buf]);
        #pragma unroll
        for (int i = 0; i < 2; i++) {
            int ch = tid + i * 256;      // 0..511
            int r = ch >> 3, c = ch & 7;
            cp16(uK + r * 144 + c * 16, Kp + (size_t)(kt + r) * HDIM + c * 8);
            cp16(uV + r * 144 + c * 16, Vp + (size_t)r * SEQ + kt + c * 8);
        }
        if (tid < 16) cp16(smem_u32(sm.mi[buf]) + tid * 16, mp + kt + tid * 4);
    };

    prefetch(0, 0);
    CP_COMMIT();

    float o[8][4] = {};
    float mrow[2] = { -1e30f, -1e30f };
    float lrow[2] = { 0.f, 0.f };

    for (int ti = 0; ti < 32; ti++) {
        int buf = ti & 1;
        if (ti + 1 < 32) prefetch(ti + 1, buf ^ 1);
        CP_COMMIT();
        if (ti < 31) { CP_WAIT1(); } else { CP_WAIT0(); }
        __syncthreads();

        const __half* ks_ = sm.Ks[buf];
        const __half* vs_ = sm.Vt[buf];

        // S = Q K^T (scale applied after)
        float s[8][4] = {};
        #pragma unroll
        for (int ks = 0; ks < 4; ks++) {
            int abase = (qb + (lane >> 2)) * 72 + ks * 16 + 2 * (lane & 3);
            uint32_t a0 = *(const uint32_t*)&sm.Qs[abase];
            uint32_t a1 = *(const uint32_t*)&sm.Qs[abase + 8 * 72];
            uint32_t a2 = *(const uint32_t*)&sm.Qs[abase + 8];
            uint32_t a3 = *(const uint32_t*)&sm.Qs[abase + 8 * 72 + 8];
            #pragma unroll
            for (int nt = 0; nt < 8; nt++) {
                int nb = (nt * 8 + (lane >> 2)) * 72 + ks * 16 + 2 * (lane & 3);
                uint32_t b0 = *(const uint32_t*)&ks_[nb];
                uint32_t b1 = *(const uint32_t*)&ks_[nb + 8];
                mma16(s[nt], a0, a1, a2, a3, b0, b1);
            }
        }

        // scale + mask
        #pragma unroll
        for (int nt = 0; nt < 8; nt++) {
            int2 mv = *(const int2*)&sm.mi[buf][nt * 8 + jc];
            float m0 = mv.x ? -1e30f : 0.f;
            float m1 = mv.y ? -1e30f : 0.f;
            s[nt][0] = s[nt][0] * 0.125f + m0;
            s[nt][1] = s[nt][1] * 0.125f + m1;
            s[nt][2] = s[nt][2] * 0.125f + m0;
            s[nt][3] = s[nt][3] * 0.125f + m1;
        }

        // online softmax (per half-row)
        #pragma unroll
        for (int h = 0; h < 2; h++) {
            float mx = -1e30f;
            #pragma unroll
            for (int nt = 0; nt < 8; nt++)
                mx = fmaxf(mx, fmaxf(s[nt][2 * h], s[nt][2 * h + 1]));
            mx = fmaxf(mx, __shfl_xor_sync(0xffffffffu, mx, 1));
            mx = fmaxf(mx, __shfl_xor_sync(0xffffffffu, mx, 2));
            float mnew = fmaxf(mrow[h], mx);
            float alpha = __expf(mrow[h] - mnew);
            mrow[h] = mnew;
            float rs = 0.f;
            #pragma unroll
            for (int nt = 0; nt < 8; nt++) {
                s[nt][2 * h]     = __expf(s[nt][2 * h]     - mnew);
                s[nt][2 * h + 1] = __expf(s[nt][2 * h + 1] - mnew);
                rs += s[nt][2 * h] + s[nt][2 * h + 1];
            }
            rs += __shfl_xor_sync(0xffffffffu, rs, 1);
            rs += __shfl_xor_sync(0xffffffffu, rs, 2);
            lrow[h] = lrow[h] * alpha + rs;
            #pragma unroll
            for (int nt = 0; nt < 8; nt++) {
                o[nt][2 * h]     *= alpha;
                o[nt][2 * h + 1] *= alpha;
            }
        }

        // P -> smem as half2 (warp-private q rows)
        #pragma unroll
        for (int h = 0; h < 2; h++) {
            int pr = (qb + (lane >> 2) + 8 * h) * 72;
            #pragma unroll
            for (int nt = 0; nt < 8; nt++) {
                __half2 hv = __floats2half2_rn(s[nt][2 * h], s[nt][2 * h + 1]);
                *(__half2*)&sm.Ps[pr + nt * 8 + jc] = hv;
            }
        }
        __syncwarp();

        // O += P V
        #pragma unroll
        for (int ks = 0; ks < 4; ks++) {
            int abase = (qb + (lane >> 2)) * 72 + ks * 16 + 2 * (lane & 3);
            uint32_t a0 = *(const uint32_t*)&sm.Ps[abase];
            uint32_t a1 = *(const uint32_t*)&sm.Ps[abase + 8 * 72];
            uint32_t a2 = *(const uint32_t*)&sm.Ps[abase + 8];
            uint32_t a3 = *(const uint32_t*)&sm.Ps[abase + 8 * 72 + 8];
            #pragma unroll
            for (int nt = 0; nt < 8; nt++) {
                int vb = (nt * 8 + (lane >> 2)) * 72 + ks * 16 + 2 * (lane & 3);
                uint32_t b0 = *(const uint32_t*)&vs_[vb];
                uint32_t b1 = *(const uint32_t*)&vs_[vb + 8];
                mma16(o[nt], a0, a1, a2, a3, b0, b1);
            }
        }
        __syncthreads();
    }

    // epilogue: normalize, write half [B,T,C]
    #pragma unroll
    for (int h = 0; h < 2; h++) {
        float inv = 1.f / lrow[h];
        int q = q0 + qb + (lane >> 2) + 8 * h;
        #pragma unroll
        for (int nt = 0; nt < 8; nt++) {
            __half2 hv = __floats2half2_rn(o[nt][2 * h] * inv, o[nt][2 * h + 1] * inv);
            *(__half2*)&Y[((size_t)b * SEQ + q) * EMBED + hh * HDIM + nt * 8 + jc] = hv;
        }
    }
}

// ---------------- launch ----------------
extern "C" void kernel_launch(void* const* d_in, const int* in_sizes, int n_in,
                              void* d_out, int out_size)
{
    const float* x    = (const float*)d_in[0];
    const int*   mask = (const int*)  d_in[1];
    const float* Wk   = (const float*)d_in[2];
    const float* bk   = (const float*)d_in[3];
    const float* Wq   = (const float*)d_in[4];
    const float* bq   = (const float*)d_in[5];
    const float* Wv   = (const float*)d_in[6];
    const float* bv   = (const float*)d_in[7];
    const float* Wo   = (const float*)d_in[8];
    const float* bo   = (const float*)d_in[9];
    float* out = (float*)d_out;

    __half *xh, *wq, *wk, *wv, *wo, *qh, *kh, *vt, *yh;
    cudaGetSymbolAddress((void**)&xh, g_xh);
    cudaGetSymbolAddress((void**)&wq, g_wq);
    cudaGetSymbolAddress((void**)&wk, g_wk);
    cudaGetSymbolAddress((void**)&wv, g_wv);
    cudaGetSymbolAddress((void**)&wo, g_wo);
    cudaGetSymbolAddress((void**)&qh, g_qh);
    cudaGetSymbolAddress((void**)&kh, g_kh);
    cudaGetSymbolAddress((void**)&vt, g_vt);
    cudaGetSymbolAddress((void**)&yh, g_yh);

    cudaFuncSetAttribute(gemm_h<0>, cudaFuncAttributeMaxDynamicSharedMemorySize, GSMEM_TOTAL);
    cudaFuncSetAttribute(gemm_h<1>, cudaFuncAttributeMaxDynamicSharedMemorySize, GSMEM_TOTAL);
    cudaFuncSetAttribute(gemm_h<2>, cudaFuncAttributeMaxDynamicSharedMemorySize, GSMEM_TOTAL);
    cudaFuncSetAttribute(attn_h, cudaFuncAttributeMaxDynamicSharedMemorySize, (int)sizeof(AttnSmemH));

    // prep: fp32 -> fp16
    f32_to_f16<<<512, 256>>>((const float4*)x,  (uint2*)xh, MROWS * EMBED / 4);
    f32_to_f16<<<256, 256>>>((const float4*)Wq, (uint2*)wq, EMBED * EMBED / 4);
    f32_to_f16<<<256, 256>>>((const float4*)Wk, (uint2*)wk, EMBED * EMBED / 4);
    f32_to_f16<<<256, 256>>>((const float4*)Wv, (uint2*)wv, EMBED * EMBED / 4);
    f32_to_f16<<<256, 256>>>((const float4*)Wo, (uint2*)wo, EMBED * EMBED / 4);

    dim3 gblk(EMBED / 128, MROWS / 128);   // (8, 64)
    gemm_h<0><<<gblk, 256, GSMEM_TOTAL>>>(xh, wq, bq, qh);
    gemm_h<0><<<gblk, 256, GSMEM_TOTAL>>>(xh, wk, bk, kh);
    gemm_h<1><<<gblk, 256, GSMEM_TOTAL>>>(xh, wv, bv, vt);

    dim3 gattn(SEQ / 128, BATCH * NHEAD);  // (16, 64)
    attn_h<<<gattn, 256, sizeof(AttnSmemH)>>>(qh, kh, vt, mask, yh);

    gemm_h<2><<<gblk, 256, GSMEM_TOTAL>>>(yh, wo, bo, out);
}

// round 6
// speedup vs baseline: 6.2739x; 1.1293x over previous
#include <cuda_runtime.h>
#include <cuda_fp16.h>
#include <cstdint>
#include <cstddef>

// Problem constants
#define BATCH 4
#define SEQ   2048
#define EMBED 1024
#define NHEAD 16
#define HDIM  64
#define MROWS (BATCH*SEQ)   // 8192

// ---------------- scratch (static device arrays; no allocation) ----------------
__device__ __half g_xh[MROWS * EMBED];   // x  fp16 [M,K]
__device__ __half g_wq[EMBED * EMBED];   // W  fp16 [N,K]
__device__ __half g_wk[EMBED * EMBED];
__device__ __half g_wv[EMBED * EMBED];
__device__ __half g_wo[EMBED * EMBED];
__device__ __half g_qh[MROWS * EMBED];   // [B,H,T,D]
__device__ __half g_kh[MROWS * EMBED];   // [B,H,T,D]
__device__ __half g_vt[MROWS * EMBED];   // [B,H,D,T]  (transposed V)
__device__ __half g_yh[MROWS * EMBED];   // [B,T,C]

// ---------------- helpers ----------------
__device__ __forceinline__ uint32_t smem_u32(const void* p) {
    uint32_t a;
    asm("{ .reg .u64 t; cvta.to.shared.u64 t, %1; cvt.u32.u64 %0, t; }" : "=r"(a) : "l"(p));
    return a;
}
__device__ __forceinline__ void cp16(uint32_t dst, const void* src) {
    asm volatile("cp.async.cg.shared.global [%0], [%1], 16;" :: "r"(dst), "l"(src));
}
#define CP_COMMIT() asm volatile("cp.async.commit_group;" ::: "memory")
#define CP_WAIT(n)  asm volatile("cp.async.wait_group %0;" :: "n"(n) : "memory")

__device__ __forceinline__ void mma16(float* c,
                                      uint32_t a0, uint32_t a1, uint32_t a2, uint32_t a3,
                                      uint32_t b0, uint32_t b1) {
    asm volatile(
        "mma.sync.aligned.m16n8k16.row.col.f32.f16.f16.f32 "
        "{%0,%1,%2,%3}, {%4,%5,%6,%7}, {%8,%9}, {%0,%1,%2,%3};\n"
        : "+f"(c[0]), "+f"(c[1]), "+f"(c[2]), "+f"(c[3])
        : "r"(a0), "r"(a1), "r"(a2), "r"(a3), "r"(b0), "r"(b1));
}
__device__ __forceinline__ void ldsm4(uint32_t& r0, uint32_t& r1, uint32_t& r2, uint32_t& r3,
                                      uint32_t addr) {
    asm volatile("ldmatrix.sync.aligned.m8n8.x4.shared.b16 {%0,%1,%2,%3}, [%4];"
                 : "=r"(r0), "=r"(r1), "=r"(r2), "=r"(r3) : "r"(addr));
}

// ---------------- prep: fp32 -> fp16, all 5 tensors in one launch ----------------
#define N4X (MROWS * EMBED / 4)      // 2097152
#define N4W (EMBED * EMBED / 4)      // 262144
__global__ void conv_all(const float4* __restrict__ x,
                         const float4* __restrict__ wq, const float4* __restrict__ wk,
                         const float4* __restrict__ wv, const float4* __restrict__ wo,
                         uint2* __restrict__ xh,
                         uint2* __restrict__ oq, uint2* __restrict__ ok,
                         uint2* __restrict__ ov, uint2* __restrict__ oo) {
    int total = N4X + 4 * N4W;
    for (int i = blockIdx.x * blockDim.x + threadIdx.x; i < total; i += gridDim.x * blockDim.x) {
        const float4* src; uint2* dst; int j;
        if (i < N4X) { src = x; dst = xh; j = i; }
        else {
            j = i - N4X;
            int wsel = j >> 18;                // /N4W
            j &= (N4W - 1);
            src = (wsel == 0) ? wq : (wsel == 1) ? wk : (wsel == 2) ? wv : wo;
            dst = (wsel == 0) ? oq : (wsel == 1) ? ok : (wsel == 2) ? ov : oo;
        }
        float4 v = src[j];
        __half2 h01 = __floats2half2_rn(v.x, v.y);
        __half2 h23 = __floats2half2_rn(v.z, v.w);
        uint2 o = { *(uint32_t*)&h01, *(uint32_t*)&h23 };
        dst[j] = o;
    }
}

// ---------------- fp16 GEMM: C = A @ B^T + bias ----------------
// CTA tile 128x128, k-tile 32, 4-stage cp.async, ldmatrix fragments.
// smem row stride 40 halves (80B): ldmatrix rows hit distinct banks.
// EPI: 0 = half out remapped [B,H,T,D]; 1 = half out transposed [B,H,D,T]; 2 = fp32 [M,N].
#define GSTAGE_B 20480                       // bytes per stage (A 10240 + B 10240)
#define GSMEM_TOTAL (4 * GSTAGE_B)           // 81920

template<int EPI>
__global__ __launch_bounds__(256)
void gemm_h(const __half* __restrict__ A, const __half* __restrict__ Bm,
            const float* __restrict__ bias, void* __restrict__ Cout)
{
    const int K = EMBED;
    extern __shared__ __half sh[];
    uint32_t sbase = smem_u32(sh);

    int tid = threadIdx.x, lane = tid & 31, w = tid >> 5;
    int wm = (w >> 2) * 64, wn = (w & 3) * 32;
    int bm = blockIdx.y * 128, bn = blockIdx.x * 128;

    const __half* Ab = A + (size_t)bm * K;
    const __half* Bb = Bm + (size_t)bn * K;

    auto fill = [&](int st, int kt) {
        uint32_t sA = sbase + st * GSTAGE_B;
        #pragma unroll
        for (int i = 0; i < 2; i++) {
            int ch = tid + i * 256;          // 0..511
            int r = ch >> 2, c = ch & 3;
            cp16(sA + r * 80 + c * 16,         Ab + (size_t)r * K + kt * 32 + c * 8);
            cp16(sA + 10240 + r * 80 + c * 16, Bb + (size_t)r * K + kt * 32 + c * 8);
        }
    };

    // ldmatrix per-lane offsets (within tile, bytes)
    int a_off = (lane & 15) * 80 + (lane >> 4) * 16;           // rows 0-15, k halves
    int b_off = ((lane >> 4) * 8 + (lane & 7)) * 80 + (((lane >> 3) & 1)) * 16; // n rows + k half

    float acc[4][4][4] = {};

    #pragma unroll
    for (int p = 0; p < 3; p++) { fill(p, p); CP_COMMIT(); }

    for (int ci = 0; ci < 32; ci++) {
        CP_WAIT(2);
        __syncthreads();
        if (ci + 3 < 32) fill((ci + 3) & 3, ci + 3);
        CP_COMMIT();

        uint32_t uS = sbase + (ci & 3) * GSTAGE_B;
        uint32_t uA = uS, uB = uS + 10240;
        #pragma unroll
        for (int ks = 0; ks < 2; ks++) {
            uint32_t afr[4][4];
            #pragma unroll
            for (int mt = 0; mt < 4; mt++)
                ldsm4(afr[mt][0], afr[mt][1], afr[mt][2], afr[mt][3],
                      uA + (wm + mt * 16) * 80 + ks * 32 + a_off);
            #pragma unroll
            for (int p = 0; p < 2; p++) {     // nt pairs: (2p, 2p+1)
                uint32_t b0a, b1a, b0b, b1b;
                ldsm4(b0a, b1a, b0b, b1b,
                      uB + (wn + p * 16) * 80 + ks * 32 + b_off);
                #pragma unroll
                for (int mt = 0; mt < 4; mt++) {
                    mma16(acc[mt][2 * p],     afr[mt][0], afr[mt][1], afr[mt][2], afr[mt][3], b0a, b1a);
                    mma16(acc[mt][2 * p + 1], afr[mt][0], afr[mt][1], afr[mt][2], afr[mt][3], b0b, b1b);
                }
            }
        }
    }

    int jc = 2 * (lane & 3);
    if (EPI == 1) {
        // transpose via smem: tile[n_local][m_local], stride 136 halves
        __syncthreads();
        #pragma unroll
        for (int mt = 0; mt < 4; mt++)
            #pragma unroll
            for (int h = 0; h < 2; h++) {
                int ml = wm + mt * 16 + (lane >> 2) + 8 * h;
                #pragma unroll
                for (int nt = 0; nt < 4; nt++) {
                    int nl = wn + nt * 8 + jc;
                    float2 bv = *(const float2*)&bias[bn + nl];
                    sh[nl * 136 + ml]       = __float2half_rn(acc[mt][nt][2 * h]     + bv.x);
                    sh[(nl + 1) * 136 + ml] = __float2half_rn(acc[mt][nt][2 * h + 1] + bv.y);
                }
            }
        __syncthreads();
        // coalesced write-out: row n -> [B,H,D,T]
        __half* o = (__half*)Cout;
        int b_ = bm >> 11, t0 = bm & (SEQ - 1);
        int r = tid >> 1, c0 = (tid & 1) * 64;
        int n = bn + r, h_ = n >> 6, d_ = n & 63;
        const uint4* src = (const uint4*)&sh[r * 136 + c0];
        uint4* dst = (uint4*)&o[((size_t)(b_ * NHEAD + h_) * HDIM + d_) * SEQ + t0 + c0];
        #pragma unroll
        for (int i = 0; i < 8; i++) dst[i] = src[i];
    } else {
        #pragma unroll
        for (int mt = 0; mt < 4; mt++)
            #pragma unroll
            for (int h = 0; h < 2; h++) {
                int m = bm + wm + mt * 16 + (lane >> 2) + 8 * h;
                #pragma unroll
                for (int nt = 0; nt < 4; nt++) {
                    int n = bn + wn + nt * 8 + jc;
                    float2 bv = *(const float2*)&bias[n];
                    float v0 = acc[mt][nt][2 * h]     + bv.x;
                    float v1 = acc[mt][nt][2 * h + 1] + bv.y;
                    if (EPI == 0) {
                        int b_ = m >> 11, t_ = m & (SEQ - 1);
                        int h_ = n >> 6, d_ = n & 63;
                        __half2 hv = __floats2half2_rn(v0, v1);
                        *(__half2*)&((__half*)Cout)[(((size_t)b_ * NHEAD + h_) * SEQ + t_) * HDIM + d_] = hv;
                    } else {
                        float2 v = { v0, v1 };
                        *(float2*)&((float*)Cout)[(size_t)m * EMBED + n] = v;
                    }
                }
            }
    }
}

// ---------------- fp16 flash attention (ldmatrix + single-sync pipeline) ----------------
// 128 queries/CTA, 8 warps x 16 q-rows, key tiles of 64, D=64. Stride 72 halves (144B).
struct AttnSmemH {
    __half Qs[128 * 72];      // [q][d]
    __half Ks[2][64 * 72];    // [key][d]   double-buffered
    __half Vt[2][64 * 72];    // [d][key]   double-buffered
    __half Ps[128 * 72];      // [q][key]
    int    mi[2][64];
};

__global__ __launch_bounds__(256)
void attn_h(const __half* __restrict__ Q, const __half* __restrict__ Kh,
            const __half* __restrict__ Vt, const int* __restrict__ mask,
            __half* __restrict__ Y)
{
    extern __shared__ char raw[];
    AttnSmemH& sm = *reinterpret_cast<AttnSmemH*>(raw);

    int tid = threadIdx.x, lane = tid & 31, w = tid >> 5;
    int jc = 2 * (lane & 3);
    int bh = blockIdx.y, b = bh >> 4, hh = bh & 15;
    int q0 = blockIdx.x * 128;
    int qb = w * 16;

    const __half* Qp = Q  + ((size_t)bh * SEQ + q0) * HDIM;
    const __half* Kp = Kh + (size_t)bh * SEQ * HDIM;
    const __half* Vp = Vt + (size_t)bh * HDIM * SEQ;
    const int*    mp = mask + (size_t)b * SEQ;

    uint32_t uQ = smem_u32(sm.Qs);
    uint32_t uPs = smem_u32(sm.Ps);

    // ldmatrix per-lane offsets (bytes)
    int a_off = (lane & 15) * 144 + (lane >> 4) * 16;
    int b_off = ((lane >> 4) * 8 + (lane & 7)) * 144 + (((lane >> 3) & 1)) * 16;

    // stage Q (128 x 64 halves)
    #pragma unroll
    for (int i = 0; i < 4; i++) {
        int ch = tid + i * 256;
        int r = ch >> 3, c = ch & 7;
        cp16(uQ + r * 144 + c * 16, Qp + (size_t)r * HDIM + c * 8);
    }

    auto prefetch = [&](int ti, int buf) {
        int kt = ti * 64;
        uint32_t uK = smem_u32(sm.Ks[buf]);
        uint32_t uV = smem_u32(sm.Vt[buf]);
        #pragma unroll
        for (int i = 0; i < 2; i++) {
            int ch = tid + i * 256;
            int r = ch >> 3, c = ch & 7;
            cp16(uK + r * 144 + c * 16, Kp + (size_t)(kt + r) * HDIM + c * 8);
            cp16(uV + r * 144 + c * 16, Vp + (size_t)r * SEQ + kt + c * 8);
        }
        if (tid < 16) cp16(smem_u32(sm.mi[buf]) + tid * 16, mp + kt + tid * 4);
    };

    prefetch(0, 0);
    CP_COMMIT();

    float o[8][4] = {};
    float mrow[2] = { -1e30f, -1e30f };
    float lrow[2] = { 0.f, 0.f };

    for (int ti = 0; ti < 32; ti++) {
        int buf = ti & 1;
        CP_WAIT(0);
        __syncthreads();
        if (ti + 1 < 32) prefetch(ti + 1, buf ^ 1);
        CP_COMMIT();

        uint32_t uK = smem_u32(sm.Ks[buf]);
        uint32_t uV = smem_u32(sm.Vt[buf]);

        // S = Q K^T
        float s[8][4] = {};
        #pragma unroll
        for (int ks = 0; ks < 4; ks++) {
            uint32_t a0, a1, a2, a3;
            ldsm4(a0, a1, a2, a3, uQ + qb * 144 + ks * 32 + a_off);
            #pragma unroll
            for (int p = 0; p < 4; p++) {
                uint32_t b0a, b1a, b0b, b1b;
                ldsm4(b0a, b1a, b0b, b1b, uK + p * 16 * 144 + ks * 32 + b_off);
                mma16(s[2 * p],     a0, a1, a2, a3, b0a, b1a);
                mma16(s[2 * p + 1], a0, a1, a2, a3, b0b, b1b);
            }
        }

        // scale + mask
        #pragma unroll
        for (int nt = 0; nt < 8; nt++) {
            int2 mv = *(const int2*)&sm.mi[buf][nt * 8 + jc];
            float m0 = mv.x ? -1e30f : 0.f;
            float m1 = mv.y ? -1e30f : 0.f;
            s[nt][0] = s[nt][0] * 0.125f + m0;
            s[nt][1] = s[nt][1] * 0.125f + m1;
            s[nt][2] = s[nt][2] * 0.125f + m0;
            s[nt][3] = s[nt][3] * 0.125f + m1;
        }

        // online softmax
        #pragma unroll
        for (int h = 0; h < 2; h++) {
            float mx = -1e30f;
            #pragma unroll
            for (int nt = 0; nt < 8; nt++)
                mx = fmaxf(mx, fmaxf(s[nt][2 * h], s[nt][2 * h + 1]));
            mx = fmaxf(mx, __shfl_xor_sync(0xffffffffu, mx, 1));
            mx = fmaxf(mx, __shfl_xor_sync(0xffffffffu, mx, 2));
            float mnew = fmaxf(mrow[h], mx);
            float alpha = __expf(mrow[h] - mnew);
            mrow[h] = mnew;
            float rs = 0.f;
            #pragma unroll
            for (int nt = 0; nt < 8; nt++) {
                s[nt][2 * h]     = __expf(s[nt][2 * h]     - mnew);
                s[nt][2 * h + 1] = __expf(s[nt][2 * h + 1] - mnew);
                rs += s[nt][2 * h] + s[nt][2 * h + 1];
            }
            rs += __shfl_xor_sync(0xffffffffu, rs, 1);
            rs += __shfl_xor_sync(0xffffffffu, rs, 2);
            lrow[h] = lrow[h] * alpha + rs;
            #pragma unroll
            for (int nt = 0; nt < 8; nt++) {
                o[nt][2 * h]     *= alpha;
                o[nt][2 * h + 1] *= alpha;
            }
        }

        // P -> smem (warp-private rows)
        #pragma unroll
        for (int h = 0; h < 2; h++) {
            int pr = (qb + (lane >> 2) + 8 * h) * 72;
            #pragma unroll
            for (int nt = 0; nt < 8; nt++) {
                __half2 hv = __floats2half2_rn(s[nt][2 * h], s[nt][2 * h + 1]);
                *(__half2*)&sm.Ps[pr + nt * 8 + jc] = hv;
            }
        }
        __syncwarp();

        // O += P V
        #pragma unroll
        for (int ks = 0; ks < 4; ks++) {
            uint32_t a0, a1, a2, a3;
            ldsm4(a0, a1, a2, a3, uPs + qb * 144 + ks * 32 + a_off);
            #pragma unroll
            for (int p = 0; p < 4; p++) {
                uint32_t b0a, b1a, b0b, b1b;
                ldsm4(b0a, b1a, b0b, b1b, uV + p * 16 * 144 + ks * 32 + b_off);
                mma16(o[2 * p],     a0, a1, a2, a3, b0a, b1a);
                mma16(o[2 * p + 1], a0, a1, a2, a3, b0b, b1b);
            }
        }
    }

    // epilogue: normalize, write half [B,T,C]
    #pragma unroll
    for (int h = 0; h < 2; h++) {
        float inv = 1.f / lrow[h];
        int q = q0 + qb + (lane >> 2) + 8 * h;
        #pragma unroll
        for (int nt = 0; nt < 8; nt++) {
            __half2 hv = __floats2half2_rn(o[nt][2 * h] * inv, o[nt][2 * h + 1] * inv);
            *(__half2*)&Y[((size_t)b * SEQ + q) * EMBED + hh * HDIM + nt * 8 + jc] = hv;
        }
    }
}

// ---------------- launch ----------------
extern "C" void kernel_launch(void* const* d_in, const int* in_sizes, int n_in,
                              void* d_out, int out_size)
{
    const float* x    = (const float*)d_in[0];
    const int*   mask = (const int*)  d_in[1];
    const float* Wk   = (const float*)d_in[2];
    const float* bk   = (const float*)d_in[3];
    const float* Wq   = (const float*)d_in[4];
    const float* bq   = (const float*)d_in[5];
    const float* Wv   = (const float*)d_in[6];
    const float* bv   = (const float*)d_in[7];
    const float* Wo   = (const float*)d_in[8];
    const float* bo   = (const float*)d_in[9];
    float* out = (float*)d_out;

    __half *xh, *wq, *wk, *wv, *wo, *qh, *kh, *vt, *yh;
    cudaGetSymbolAddress((void**)&xh, g_xh);
    cudaGetSymbolAddress((void**)&wq, g_wq);
    cudaGetSymbolAddress((void**)&wk, g_wk);
    cudaGetSymbolAddress((void**)&wv, g_wv);
    cudaGetSymbolAddress((void**)&wo, g_wo);
    cudaGetSymbolAddress((void**)&qh, g_qh);
    cudaGetSymbolAddress((void**)&kh, g_kh);
    cudaGetSymbolAddress((void**)&vt, g_vt);
    cudaGetSymbolAddress((void**)&yh, g_yh);

    cudaFuncSetAttribute(gemm_h<0>, cudaFuncAttributeMaxDynamicSharedMemorySize, GSMEM_TOTAL);
    cudaFuncSetAttribute(gemm_h<1>, cudaFuncAttributeMaxDynamicSharedMemorySize, GSMEM_TOTAL);
    cudaFuncSetAttribute(gemm_h<2>, cudaFuncAttributeMaxDynamicSharedMemorySize, GSMEM_TOTAL);
    cudaFuncSetAttribute(attn_h, cudaFuncAttributeMaxDynamicSharedMemorySize, (int)sizeof(AttnSmemH));

    conv_all<<<512, 256>>>((const float4*)x, (const float4*)Wq, (const float4*)Wk,
                           (const float4*)Wv, (const float4*)Wo,
                           (uint2*)xh, (uint2*)wq, (uint2*)wk, (uint2*)wv, (uint2*)wo);

    dim3 gblk(EMBED / 128, MROWS / 128);   // (8, 64)
    gemm_h<0><<<gblk, 256, GSMEM_TOTAL>>>(xh, wq, bq, qh);
    gemm_h<0><<<gblk, 256, GSMEM_TOTAL>>>(xh, wk, bk, kh);
    gemm_h<1><<<gblk, 256, GSMEM_TOTAL>>>(xh, wv, bv, vt);

    dim3 gattn(SEQ / 128, BATCH * NHEAD);  // (16, 64)
    attn_h<<<gattn, 256, sizeof(AttnSmemH)>>>(qh, kh, vt, mask, yh);

    gemm_h<2><<<gblk, 256, GSMEM_TOTAL>>>(yh, wo, bo, out);
}

// round 7
// speedup vs baseline: 7.1348x; 1.1372x over previous
#include <cuda_runtime.h>
#include <cuda_fp16.h>
#include <cstdint>
#include <cstddef>

// Problem constants
#define BATCH 4
#define SEQ   2048
#define EMBED 1024
#define NHEAD 16
#define HDIM  64
#define MROWS (BATCH*SEQ)   // 8192

// ---------------- scratch (static device arrays; no allocation) ----------------
__device__ __half g_xh[MROWS * EMBED];   // x  fp16 [M,K]
__device__ __half g_wq[EMBED * EMBED];   // W  fp16 [N,K]
__device__ __half g_wk[EMBED * EMBED];
__device__ __half g_wv[EMBED * EMBED];
__device__ __half g_wo[EMBED * EMBED];
__device__ __half g_qh[MROWS * EMBED];   // [B,H,T,D]
__device__ __half g_kh[MROWS * EMBED];   // [B,H,T,D]
__device__ __half g_vt[MROWS * EMBED];   // [B,H,D,T]  (transposed V)
__device__ __half g_yh[MROWS * EMBED];   // [B,T,C]

// ---------------- helpers ----------------
__device__ __forceinline__ uint32_t smem_u32(const void* p) {
    uint32_t a;
    asm("{ .reg .u64 t; cvta.to.shared.u64 t, %1; cvt.u32.u64 %0, t; }" : "=r"(a) : "l"(p));
    return a;
}
__device__ __forceinline__ void cp16(uint32_t dst, const void* src) {
    asm volatile("cp.async.cg.shared.global [%0], [%1], 16;" :: "r"(dst), "l"(src));
}
#define CP_COMMIT() asm volatile("cp.async.commit_group;" ::: "memory")
#define CP_WAIT(n)  asm volatile("cp.async.wait_group %0;" :: "n"(n) : "memory")

__device__ __forceinline__ void mma16(float* c,
                                      uint32_t a0, uint32_t a1, uint32_t a2, uint32_t a3,
                                      uint32_t b0, uint32_t b1) {
    asm volatile(
        "mma.sync.aligned.m16n8k16.row.col.f32.f16.f16.f32 "
        "{%0,%1,%2,%3}, {%4,%5,%6,%7}, {%8,%9}, {%0,%1,%2,%3};\n"
        : "+f"(c[0]), "+f"(c[1]), "+f"(c[2]), "+f"(c[3])
        : "r"(a0), "r"(a1), "r"(a2), "r"(a3), "r"(b0), "r"(b1));
}
__device__ __forceinline__ void ldsm4(uint32_t& r0, uint32_t& r1, uint32_t& r2, uint32_t& r3,
                                      uint32_t addr) {
    asm volatile("ldmatrix.sync.aligned.m8n8.x4.shared.b16 {%0,%1,%2,%3}, [%4];"
                 : "=r"(r0), "=r"(r1), "=r"(r2), "=r"(r3) : "r"(addr));
}
__device__ __forceinline__ float ex2f(float x) {
    float y;
    asm("ex2.approx.ftz.f32 %0, %1;" : "=f"(y) : "f"(x));
    return y;
}

// ---------------- prep: fp32 -> fp16, all 5 tensors in one launch ----------------
#define N4X (MROWS * EMBED / 4)      // 2097152
#define N4W (EMBED * EMBED / 4)      // 262144
__global__ void conv_all(const float4* __restrict__ x,
                         const float4* __restrict__ wq, const float4* __restrict__ wk,
                         const float4* __restrict__ wv, const float4* __restrict__ wo,
                         uint2* __restrict__ xh,
                         uint2* __restrict__ oq, uint2* __restrict__ ok,
                         uint2* __restrict__ ov, uint2* __restrict__ oo) {
    int total = N4X + 4 * N4W;
    for (int i = blockIdx.x * blockDim.x + threadIdx.x; i < total; i += gridDim.x * blockDim.x) {
        const float4* src; uint2* dst; int j;
        if (i < N4X) { src = x; dst = xh; j = i; }
        else {
            j = i - N4X;
            int wsel = j >> 18;
            j &= (N4W - 1);
            src = (wsel == 0) ? wq : (wsel == 1) ? wk : (wsel == 2) ? wv : wo;
            dst = (wsel == 0) ? oq : (wsel == 1) ? ok : (wsel == 2) ? ov : oo;
        }
        float4 v = src[j];
        __half2 h01 = __floats2half2_rn(v.x, v.y);
        __half2 h23 = __floats2half2_rn(v.z, v.w);
        uint2 o = { *(uint32_t*)&h01, *(uint32_t*)&h23 };
        dst[j] = o;
    }
}

// ---------------- fp16 GEMM mainloop (shared by QKV + out-proj) ----------------
// CTA tile 128x128, k-tile 64, 3-stage cp.async, ldmatrix. Row stride 144B.
#define SROWB 144
#define GT_BYTES (128 * SROWB)       // 18432 per operand tile
#define GSTG (2 * GT_BYTES)          // 36864 per stage
#define GSMEM (3 * GSTG)             // 110592

__device__ __forceinline__ void gemm_main(const __half* __restrict__ Ab,
                                          const __half* __restrict__ Bb,
                                          uint32_t sbase, int tid, int lane, int w,
                                          float acc[4][4][4])
{
    const int K = EMBED;
    int wm = (w >> 2) * 64, wn = (w & 3) * 32;
    int a_off = (lane & 15) * SROWB + (lane >> 4) * 16;
    int b_off = ((lane >> 4) * 8 + (lane & 7)) * SROWB + ((lane >> 3) & 1) * 16;

    auto fill = [&](int st, int kt) {
        uint32_t sA = sbase + st * GSTG;
        #pragma unroll
        for (int i = 0; i < 4; i++) {
            int ch = tid + i * 256;          // 0..1023
            int r = ch >> 3, c = ch & 7;
            cp16(sA + r * SROWB + c * 16,            Ab + (size_t)r * K + kt * 64 + c * 8);
            cp16(sA + GT_BYTES + r * SROWB + c * 16, Bb + (size_t)r * K + kt * 64 + c * 8);
        }
    };

    fill(0, 0); CP_COMMIT();
    fill(1, 1); CP_COMMIT();

    for (int ci = 0; ci < 16; ci++) {
        CP_WAIT(1);
        __syncthreads();
        if (ci + 2 < 16) {
            int st = (ci + 2) % 3;
            fill(st, ci + 2);
        }
        CP_COMMIT();

        uint32_t uA = sbase + (ci % 3) * GSTG;
        uint32_t uB = uA + GT_BYTES;
        #pragma unroll
        for (int ks = 0; ks < 4; ks++) {
            uint32_t afr[4][4];
            #pragma unroll
            for (int mt = 0; mt < 4; mt++)
                ldsm4(afr[mt][0], afr[mt][1], afr[mt][2], afr[mt][3],
                      uA + (wm + mt * 16) * SROWB + ks * 32 + a_off);
            #pragma unroll
            for (int p = 0; p < 2; p++) {
                uint32_t b0a, b1a, b0b, b1b;
                ldsm4(b0a, b1a, b0b, b1b,
                      uB + (wn + p * 16) * SROWB + ks * 32 + b_off);
                #pragma unroll
                for (int mt = 0; mt < 4; mt++) {
                    mma16(acc[mt][2 * p],     afr[mt][0], afr[mt][1], afr[mt][2], afr[mt][3], b0a, b1a);
                    mma16(acc[mt][2 * p + 1], afr[mt][0], afr[mt][1], afr[mt][2], afr[mt][3], b0b, b1b);
                }
            }
        }
    }
}

// ---------------- fused QKV projection (gridDim.z = 3) ----------------
__global__ __launch_bounds__(256, 2)
void gemm_qkv(const __half* __restrict__ A,
              const __half* __restrict__ wq, const __half* __restrict__ wk,
              const __half* __restrict__ wv,
              const float* __restrict__ bq, const float* __restrict__ bk,
              const float* __restrict__ bv,
              __half* __restrict__ qh, __half* __restrict__ kh, __half* __restrict__ vt)
{
    extern __shared__ __half sh[];
    uint32_t sbase = smem_u32(sh);
    int tid = threadIdx.x, lane = tid & 31, w = tid >> 5;
    int wm = (w >> 2) * 64, wn = (w & 3) * 32;
    int bm = blockIdx.y * 128, bn = blockIdx.x * 128;
    int z = blockIdx.z;

    const __half* Bw = (z == 0) ? wq : (z == 1) ? wk : wv;
    const float* bias = (z == 0) ? bq : (z == 1) ? bk : bv;

    float acc[4][4][4] = {};
    gemm_main(A + (size_t)bm * EMBED, Bw + (size_t)bn * EMBED, sbase, tid, lane, w, acc);

    int jc = 2 * (lane & 3);
    if (z < 2) {
        __half* Cout = (z == 0) ? qh : kh;
        #pragma unroll
        for (int mt = 0; mt < 4; mt++)
            #pragma unroll
            for (int h = 0; h < 2; h++) {
                int m = bm + wm + mt * 16 + (lane >> 2) + 8 * h;
                int b_ = m >> 11, t_ = m & (SEQ - 1);
                #pragma unroll
                for (int nt = 0; nt < 4; nt++) {
                    int n = bn + wn + nt * 8 + jc;
                    float2 bv2 = *(const float2*)&bias[n];
                    __half2 hv = __floats2half2_rn(acc[mt][nt][2 * h] + bv2.x,
                                                   acc[mt][nt][2 * h + 1] + bv2.y);
                    int h_ = n >> 6, d_ = n & 63;
                    *(__half2*)&Cout[(((size_t)b_ * NHEAD + h_) * SEQ + t_) * HDIM + d_] = hv;
                }
            }
    } else {
        // V: transpose via smem, write [B,H,D,T]
        __syncthreads();
        #pragma unroll
        for (int mt = 0; mt < 4; mt++)
            #pragma unroll
            for (int h = 0; h < 2; h++) {
                int ml = wm + mt * 16 + (lane >> 2) + 8 * h;
                #pragma unroll
                for (int nt = 0; nt < 4; nt++) {
                    int nl = wn + nt * 8 + jc;
                    float2 bv2 = *(const float2*)&bias[bn + nl];
                    sh[nl * 136 + ml]       = __float2half_rn(acc[mt][nt][2 * h]     + bv2.x);
                    sh[(nl + 1) * 136 + ml] = __float2half_rn(acc[mt][nt][2 * h + 1] + bv2.y);
                }
            }
        __syncthreads();
        int b_ = bm >> 11, t0 = bm & (SEQ - 1);
        int r = tid >> 1, c0 = (tid & 1) * 64;
        int n = bn + r, h_ = n >> 6, d_ = n & 63;
        const uint4* src = (const uint4*)&sh[r * 136 + c0];
        uint4* dst = (uint4*)&vt[((size_t)(b_ * NHEAD + h_) * HDIM + d_) * SEQ + t0 + c0];
        #pragma unroll
        for (int i = 0; i < 8; i++) dst[i] = src[i];
    }
}

// ---------------- output projection: fp32 out ----------------
__global__ __launch_bounds__(256, 2)
void gemm_o(const __half* __restrict__ A, const __half* __restrict__ Bm,
            const float* __restrict__ bias, float* __restrict__ Cout)
{
    extern __shared__ __half sh[];
    uint32_t sbase = smem_u32(sh);
    int tid = threadIdx.x, lane = tid & 31, w = tid >> 5;
    int wm = (w >> 2) * 64, wn = (w & 3) * 32;
    int bm = blockIdx.y * 128, bn = blockIdx.x * 128;

    float acc[4][4][4] = {};
    gemm_main(A + (size_t)bm * EMBED, Bm + (size_t)bn * EMBED, sbase, tid, lane, w, acc);

    int jc = 2 * (lane & 3);
    #pragma unroll
    for (int mt = 0; mt < 4; mt++)
        #pragma unroll
        for (int h = 0; h < 2; h++) {
            int m = bm + wm + mt * 16 + (lane >> 2) + 8 * h;
            #pragma unroll
            for (int nt = 0; nt < 4; nt++) {
                int n = bn + wn + nt * 8 + jc;
                float2 bv2 = *(const float2*)&bias[n];
                float2 v = { acc[mt][nt][2 * h] + bv2.x, acc[mt][nt][2 * h + 1] + bv2.y };
                *(float2*)&Cout[(size_t)m * EMBED + n] = v;
            }
        }
}

// ---------------- fp16 flash attention (ldmatrix + base-2 softmax) ----------------
#define SCALE_L2E 0.18033688011112042f   // 0.125 * log2(e)
#define NEGINF2   -1e30f

struct AttnSmemH {
    __half Qs[128 * 72];
    __half Ks[2][64 * 72];
    __half Vt[2][64 * 72];
    __half Ps[128 * 72];
    int    mi[2][64];
};

__global__ __launch_bounds__(256)
void attn_h(const __half* __restrict__ Q, const __half* __restrict__ Kh,
            const __half* __restrict__ Vt, const int* __restrict__ mask,
            __half* __restrict__ Y)
{
    extern __shared__ char raw[];
    AttnSmemH& sm = *reinterpret_cast<AttnSmemH*>(raw);

    int tid = threadIdx.x, lane = tid & 31, w = tid >> 5;
    int jc = 2 * (lane & 3);
    int bh = blockIdx.y, b = bh >> 4, hh = bh & 15;
    int q0 = blockIdx.x * 128;
    int qb = w * 16;

    const __half* Qp = Q  + ((size_t)bh * SEQ + q0) * HDIM;
    const __half* Kp = Kh + (size_t)bh * SEQ * HDIM;
    const __half* Vp = Vt + (size_t)bh * HDIM * SEQ;
    const int*    mp = mask + (size_t)b * SEQ;

    uint32_t uQ = smem_u32(sm.Qs);
    uint32_t uPs = smem_u32(sm.Ps);

    int a_off = (lane & 15) * 144 + (lane >> 4) * 16;
    int b_off = ((lane >> 4) * 8 + (lane & 7)) * 144 + ((lane >> 3) & 1) * 16;

    #pragma unroll
    for (int i = 0; i < 4; i++) {
        int ch = tid + i * 256;
        int r = ch >> 3, c = ch & 7;
        cp16(uQ + r * 144 + c * 16, Qp + (size_t)r * HDIM + c * 8);
    }

    auto prefetch = [&](int ti, int buf) {
        int kt = ti * 64;
        uint32_t uK = smem_u32(sm.Ks[buf]);
        uint32_t uV = smem_u32(sm.Vt[buf]);
        #pragma unroll
        for (int i = 0; i < 2; i++) {
            int ch = tid + i * 256;
            int r = ch >> 3, c = ch & 7;
            cp16(uK + r * 144 + c * 16, Kp + (size_t)(kt + r) * HDIM + c * 8);
            cp16(uV + r * 144 + c * 16, Vp + (size_t)r * SEQ + kt + c * 8);
        }
        if (tid < 16) cp16(smem_u32(sm.mi[buf]) + tid * 16, mp + kt + tid * 4);
    };

    prefetch(0, 0);
    CP_COMMIT();

    float o[8][4] = {};
    float mrow[2] = { NEGINF2, NEGINF2 };   // log2-domain running max
    float lrow[2] = { 0.f, 0.f };

    for (int ti = 0; ti < 32; ti++) {
        int buf = ti & 1;
        CP_WAIT(0);
        __syncthreads();
        if (ti + 1 < 32) prefetch(ti + 1, buf ^ 1);
        CP_COMMIT();

        uint32_t uK = smem_u32(sm.Ks[buf]);
        uint32_t uV = smem_u32(sm.Vt[buf]);

        // S = Q K^T
        float s[8][4] = {};
        #pragma unroll
        for (int ks = 0; ks < 4; ks++) {
            uint32_t a0, a1, a2, a3;
            ldsm4(a0, a1, a2, a3, uQ + qb * 144 + ks * 32 + a_off);
            #pragma unroll
            for (int p = 0; p < 4; p++) {
                uint32_t b0a, b1a, b0b, b1b;
                ldsm4(b0a, b1a, b0b, b1b, uK + p * 16 * 144 + ks * 32 + b_off);
                mma16(s[2 * p],     a0, a1, a2, a3, b0a, b1a);
                mma16(s[2 * p + 1], a0, a1, a2, a3, b0b, b1b);
            }
        }

        // scale into log2 domain + mask
        #pragma unroll
        for (int nt = 0; nt < 8; nt++) {
            int2 mv = *(const int2*)&sm.mi[buf][nt * 8 + jc];
            float m0 = mv.x ? NEGINF2 : 0.f;
            float m1 = mv.y ? NEGINF2 : 0.f;
            s[nt][0] = s[nt][0] * SCALE_L2E + m0;
            s[nt][1] = s[nt][1] * SCALE_L2E + m1;
            s[nt][2] = s[nt][2] * SCALE_L2E + m0;
            s[nt][3] = s[nt][3] * SCALE_L2E + m1;
        }

        // online softmax (base-2)
        #pragma unroll
        for (int h = 0; h < 2; h++) {
            float mx = NEGINF2;
            #pragma unroll
            for (int nt = 0; nt < 8; nt++)
                mx = fmaxf(mx, fmaxf(s[nt][2 * h], s[nt][2 * h + 1]));
            mx = fmaxf(mx, __shfl_xor_sync(0xffffffffu, mx, 1));
            mx = fmaxf(mx, __shfl_xor_sync(0xffffffffu, mx, 2));
            float mnew = fmaxf(mrow[h], mx);
            float alpha = ex2f(mrow[h] - mnew);
            mrow[h] = mnew;
            float rs = 0.f;
            #pragma unroll
            for (int nt = 0; nt < 8; nt++) {
                s[nt][2 * h]     = ex2f(s[nt][2 * h]     - mnew);
                s[nt][2 * h + 1] = ex2f(s[nt][2 * h + 1] - mnew);
                rs += s[nt][2 * h] + s[nt][2 * h + 1];
            }
            rs += __shfl_xor_sync(0xffffffffu, rs, 1);
            rs += __shfl_xor_sync(0xffffffffu, rs, 2);
            lrow[h] = lrow[h] * alpha + rs;
            #pragma unroll
            for (int nt = 0; nt < 8; nt++) {
                o[nt][2 * h]     *= alpha;
                o[nt][2 * h + 1] *= alpha;
            }
        }

        // P -> smem (warp-private rows)
        #pragma unroll
        for (int h = 0; h < 2; h++) {
            int pr = (qb + (lane >> 2) + 8 * h) * 72;
            #pragma unroll
            for (int nt = 0; nt < 8; nt++) {
                __half2 hv = __floats2half2_rn(s[nt][2 * h], s[nt][2 * h + 1]);
                *(__half2*)&sm.Ps[pr + nt * 8 + jc] = hv;
            }
        }
        __syncwarp();

        // O += P V
        #pragma unroll
        for (int ks = 0; ks < 4; ks++) {
            uint32_t a0, a1, a2, a3;
            ldsm4(a0, a1, a2, a3, uPs + qb * 144 + ks * 32 + a_off);
            #pragma unroll
            for (int p = 0; p < 4; p++) {
                uint32_t b0a, b1a, b0b, b1b;
                ldsm4(b0a, b1a, b0b, b1b, uV + p * 16 * 144 + ks * 32 + b_off);
                mma16(o[2 * p],     a0, a1, a2, a3, b0a, b1a);
                mma16(o[2 * p + 1], a0, a1, a2, a3, b0b, b1b);
            }
        }
    }

    // epilogue: normalize, write half [B,T,C]
    #pragma unroll
    for (int h = 0; h < 2; h++) {
        float inv = 1.f / lrow[h];
        int q = q0 + qb + (lane >> 2) + 8 * h;
        #pragma unroll
        for (int nt = 0; nt < 8; nt++) {
            __half2 hv = __floats2half2_rn(o[nt][2 * h] * inv, o[nt][2 * h + 1] * inv);
            *(__half2*)&Y[((size_t)b * SEQ + q) * EMBED + hh * HDIM + nt * 8 + jc] = hv;
        }
    }
}

// ---------------- launch ----------------
extern "C" void kernel_launch(void* const* d_in, const int* in_sizes, int n_in,
                              void* d_out, int out_size)
{
    const float* x    = (const float*)d_in[0];
    const int*   mask = (const int*)  d_in[1];
    const float* Wk   = (const float*)d_in[2];
    const float* bk   = (const float*)d_in[3];
    const float* Wq   = (const float*)d_in[4];
    const float* bq   = (const float*)d_in[5];
    const float* Wv   = (const float*)d_in[6];
    const float* bv   = (const float*)d_in[7];
    const float* Wo   = (const float*)d_in[8];
    const float* bo   = (const float*)d_in[9];
    float* out = (float*)d_out;

    __half *xh, *wq, *wk, *wv, *wo, *qh, *kh, *vt, *yh;
    cudaGetSymbolAddress((void**)&xh, g_xh);
    cudaGetSymbolAddress((void**)&wq, g_wq);
    cudaGetSymbolAddress((void**)&wk, g_wk);
    cudaGetSymbolAddress((void**)&wv, g_wv);
    cudaGetSymbolAddress((void**)&wo, g_wo);
    cudaGetSymbolAddress((void**)&qh, g_qh);
    cudaGetSymbolAddress((void**)&kh, g_kh);
    cudaGetSymbolAddress((void**)&vt, g_vt);
    cudaGetSymbolAddress((void**)&yh, g_yh);

    cudaFuncSetAttribute(gemm_qkv, cudaFuncAttributeMaxDynamicSharedMemorySize, GSMEM);
    cudaFuncSetAttribute(gemm_o,   cudaFuncAttributeMaxDynamicSharedMemorySize, GSMEM);
    cudaFuncSetAttribute(attn_h,   cudaFuncAttributeMaxDynamicSharedMemorySize, (int)sizeof(AttnSmemH));

    conv_all<<<512, 256>>>((const float4*)x, (const float4*)Wq, (const float4*)Wk,
                           (const float4*)Wv, (const float4*)Wo,
                           (uint2*)xh, (uint2*)wq, (uint2*)wk, (uint2*)wv, (uint2*)wo);

    dim3 gqkv(EMBED / 128, MROWS / 128, 3);   // (8, 64, 3)
    gemm_qkv<<<gqkv, 256, GSMEM>>>(xh, wq, wk, wv, bq, bk, bv, qh, kh, vt);

    dim3 gattn(SEQ / 128, BATCH * NHEAD);     // (16, 64)
    attn_h<<<gattn, 256, sizeof(AttnSmemH)>>>(qh, kh, vt, mask, yh);

    dim3 gblk(EMBED / 128, MROWS / 128);      // (8, 64)
    gemm_o<<<gblk, 256, GSMEM>>>(yh, wo, bo, out);
}

// round 8
// speedup vs baseline: 10.2522x; 1.4369x over previous
#include <cuda_runtime.h>
#include <cuda_fp16.h>
#include <cstdint>
#include <cstddef>

// Problem constants
#define BATCH 4
#define SEQ   2048
#define EMBED 1024
#define NHEAD 16
#define HDIM  64
#define MROWS (BATCH*SEQ)   // 8192

// ---------------- scratch (static device arrays; no allocation) ----------------
__device__ __half g_xh[MROWS * EMBED];   // x  fp16 [B,T,C]
__device__ __half g_xc[MROWS * EMBED];   // x compacted per batch [B,Tc,C] (zero-padded)
__device__ __half g_wq[EMBED * EMBED];
__device__ __half g_wk[EMBED * EMBED];
__device__ __half g_wv[EMBED * EMBED];
__device__ __half g_wo[EMBED * EMBED];
__device__ __half g_qh[MROWS * EMBED];   // [B,H,T,D]
__device__ __half g_kc[MROWS * EMBED];   // [B,H,Tc,D] compacted K
__device__ __half g_vc[MROWS * EMBED];   // [B,H,Tc,D] compacted V
__device__ __half g_yh[MROWS * EMBED];   // [B,T,C]
__device__ int    g_idx[BATCH * SEQ];
__device__ int    g_cnt[BATCH];

// ---------------- helpers ----------------
__device__ __forceinline__ uint32_t smem_u32(const void* p) {
    uint32_t a;
    asm("{ .reg .u64 t; cvta.to.shared.u64 t, %1; cvt.u32.u64 %0, t; }" : "=r"(a) : "l"(p));
    return a;
}
__device__ __forceinline__ void cp16(uint32_t dst, const void* src) {
    asm volatile("cp.async.cg.shared.global [%0], [%1], 16;" :: "r"(dst), "l"(src));
}
#define CP_COMMIT() asm volatile("cp.async.commit_group;" ::: "memory")
#define CP_WAIT(n)  asm volatile("cp.async.wait_group %0;" :: "n"(n) : "memory")

__device__ __forceinline__ void mma16(float* c,
                                      uint32_t a0, uint32_t a1, uint32_t a2, uint32_t a3,
                                      uint32_t b0, uint32_t b1) {
    asm volatile(
        "mma.sync.aligned.m16n8k16.row.col.f32.f16.f16.f32 "
        "{%0,%1,%2,%3}, {%4,%5,%6,%7}, {%8,%9}, {%0,%1,%2,%3};\n"
        : "+f"(c[0]), "+f"(c[1]), "+f"(c[2]), "+f"(c[3])
        : "r"(a0), "r"(a1), "r"(a2), "r"(a3), "r"(b0), "r"(b1));
}
__device__ __forceinline__ void ldsm4(uint32_t& r0, uint32_t& r1, uint32_t& r2, uint32_t& r3,
                                      uint32_t addr) {
    asm volatile("ldmatrix.sync.aligned.m8n8.x4.shared.b16 {%0,%1,%2,%3}, [%4];"
                 : "=r"(r0), "=r"(r1), "=r"(r2), "=r"(r3) : "r"(addr));
}
__device__ __forceinline__ void ldsm4t(uint32_t& r0, uint32_t& r1, uint32_t& r2, uint32_t& r3,
                                       uint32_t addr) {
    asm volatile("ldmatrix.sync.aligned.m8n8.x4.trans.shared.b16 {%0,%1,%2,%3}, [%4];"
                 : "=r"(r0), "=r"(r1), "=r"(r2), "=r"(r3) : "r"(addr));
}
__device__ __forceinline__ float ex2f(float x) {
    float y;
    asm("ex2.approx.ftz.f32 %0, %1;" : "=f"(y) : "f"(x));
    return y;
}

// ---------------- compact: per-batch indices of unmasked keys ----------------
__global__ void compact_idx(const int* __restrict__ mask, int* __restrict__ idx,
                            int* __restrict__ cnt) {
    int b = blockIdx.x, tid = threadIdx.x;
    const int* mp = mask + b * SEQ;
    __shared__ int sbuf[256];
    __shared__ int sbase;
    if (tid == 0) sbase = 0;
    __syncthreads();
    for (int c0 = 0; c0 < SEQ; c0 += 256) {
        int v = (mp[c0 + tid] == 0) ? 1 : 0;
        sbuf[tid] = v;
        __syncthreads();
        int acc = sbuf[tid];
        #pragma unroll
        for (int off = 1; off < 256; off <<= 1) {
            int t = (tid >= off) ? sbuf[tid - off] : 0;
            __syncthreads();
            acc += t;
            sbuf[tid] = acc;
            __syncthreads();
        }
        if (v) idx[b * SEQ + sbase + acc - 1] = c0 + tid;
        __syncthreads();
        if (tid == 255) sbase += sbuf[255];
        __syncthreads();
    }
    if (tid == 0) cnt[b] = sbase;
}

// ---------------- gather x rows (compacted, zero-padded to 128) ----------------
__global__ void gather_x(const __half* __restrict__ xh, __half* __restrict__ xc,
                         const int* __restrict__ idx, const int* __restrict__ cnt) {
    int b = blockIdx.y, tid = threadIdx.x;
    int j = blockIdx.x * 64 + (tid >> 2);       // output row
    int qpart = (tid & 3) * 256;                // halves offset (512B chunk)
    int nk = cnt[b];
    int pad = (nk + 127) & ~127;
    if (j >= pad) return;
    uint4* dst = (uint4*)&xc[((size_t)b * SEQ + j) * EMBED + qpart];
    if (j < nk) {
        int src = idx[b * SEQ + j];
        const uint4* s = (const uint4*)&xh[((size_t)b * SEQ + src) * EMBED + qpart];
        #pragma unroll
        for (int i = 0; i < 32; i++) dst[i] = s[i];
    } else {
        uint4 z = {0, 0, 0, 0};
        #pragma unroll
        for (int i = 0; i < 32; i++) dst[i] = z;
    }
}

// ---------------- prep: fp32 -> fp16, all 5 tensors in one launch ----------------
#define N4X (MROWS * EMBED / 4)
#define N4W (EMBED * EMBED / 4)
__global__ void conv_all(const float4* __restrict__ x,
                         const float4* __restrict__ wq, const float4* __restrict__ wk,
                         const float4* __restrict__ wv, const float4* __restrict__ wo,
                         uint2* __restrict__ xh,
                         uint2* __restrict__ oq, uint2* __restrict__ ok,
                         uint2* __restrict__ ov, uint2* __restrict__ oo) {
    int total = N4X + 4 * N4W;
    for (int i = blockIdx.x * blockDim.x + threadIdx.x; i < total; i += gridDim.x * blockDim.x) {
        const float4* src; uint2* dst; int j;
        if (i < N4X) { src = x; dst = xh; j = i; }
        else {
            j = i - N4X;
            int wsel = j >> 18;
            j &= (N4W - 1);
            src = (wsel == 0) ? wq : (wsel == 1) ? wk : (wsel == 2) ? wv : wo;
            dst = (wsel == 0) ? oq : (wsel == 1) ? ok : (wsel == 2) ? ov : oo;
        }
        float4 v = src[j];
        __half2 h01 = __floats2half2_rn(v.x, v.y);
        __half2 h23 = __floats2half2_rn(v.z, v.w);
        uint2 o = { *(uint32_t*)&h01, *(uint32_t*)&h23 };
        dst[j] = o;
    }
}

// ---------------- fp16 GEMM mainloop ----------------
#define SROWB 144
#define GT_BYTES (128 * SROWB)
#define GSTG (2 * GT_BYTES)
#define GSMEM (3 * GSTG)

__device__ __forceinline__ void gemm_main(const __half* __restrict__ Ab,
                                          const __half* __restrict__ Bb,
                                          uint32_t sbase, int tid, int lane, int w,
                                          float acc[4][4][4])
{
    const int K = EMBED;
    int wm = (w >> 2) * 64, wn = (w & 3) * 32;
    int a_off = (lane & 15) * SROWB + (lane >> 4) * 16;
    int b_off = ((lane >> 4) * 8 + (lane & 7)) * SROWB + ((lane >> 3) & 1) * 16;

    auto fill = [&](int st, int kt) {
        uint32_t sA = sbase + st * GSTG;
        #pragma unroll
        for (int i = 0; i < 4; i++) {
            int ch = tid + i * 256;
            int r = ch >> 3, c = ch & 7;
            cp16(sA + r * SROWB + c * 16,            Ab + (size_t)r * K + kt * 64 + c * 8);
            cp16(sA + GT_BYTES + r * SROWB + c * 16, Bb + (size_t)r * K + kt * 64 + c * 8);
        }
    };

    fill(0, 0); CP_COMMIT();
    fill(1, 1); CP_COMMIT();

    for (int ci = 0; ci < 16; ci++) {
        CP_WAIT(1);
        __syncthreads();
        if (ci + 2 < 16) fill((ci + 2) % 3, ci + 2);
        CP_COMMIT();

        uint32_t uA = sbase + (ci % 3) * GSTG;
        uint32_t uB = uA + GT_BYTES;
        #pragma unroll
        for (int ks = 0; ks < 4; ks++) {
            uint32_t afr[4][4];
            #pragma unroll
            for (int mt = 0; mt < 4; mt++)
                ldsm4(afr[mt][0], afr[mt][1], afr[mt][2], afr[mt][3],
                      uA + (wm + mt * 16) * SROWB + ks * 32 + a_off);
            #pragma unroll
            for (int p = 0; p < 2; p++) {
                uint32_t b0a, b1a, b0b, b1b;
                ldsm4(b0a, b1a, b0b, b1b,
                      uB + (wn + p * 16) * SROWB + ks * 32 + b_off);
                #pragma unroll
                for (int mt = 0; mt < 4; mt++) {
                    mma16(acc[mt][2 * p],     afr[mt][0], afr[mt][1], afr[mt][2], afr[mt][3], b0a, b1a);
                    mma16(acc[mt][2 * p + 1], afr[mt][0], afr[mt][1], afr[mt][2], afr[mt][3], b0b, b1b);
                }
            }
        }
    }
}

// ---------------- fused QKV projection (z=0: Q on full x; z=1,2: K,V on compacted x) ----------------
__global__ __launch_bounds__(256, 2)
void gemm_qkv(const __half* __restrict__ xh, const __half* __restrict__ xc,
              const __half* __restrict__ wq, const __half* __restrict__ wk,
              const __half* __restrict__ wv,
              const float* __restrict__ bq, const float* __restrict__ bk,
              const float* __restrict__ bv,
              __half* __restrict__ qh, __half* __restrict__ kc, __half* __restrict__ vc,
              const int* __restrict__ cnt)
{
    extern __shared__ __half sh[];
    uint32_t sbase = smem_u32(sh);
    int tid = threadIdx.x, lane = tid & 31, w = tid >> 5;
    int wm = (w >> 2) * 64, wn = (w & 3) * 32;
    int bm = blockIdx.y * 128, bn = blockIdx.x * 128;
    int z = blockIdx.z;

    int batch = bm >> 11, loc = bm & (SEQ - 1);
    if (z > 0) {
        int pad = (cnt[batch] + 127) & ~127;
        if (loc >= pad) return;           // whole CTA exits
    }

    const __half* A = (z == 0) ? xh : xc;
    const __half* Bw = (z == 0) ? wq : (z == 1) ? wk : wv;
    const float* bias = (z == 0) ? bq : (z == 1) ? bk : bv;
    __half* Cout = (z == 0) ? qh : (z == 1) ? kc : vc;

    float acc[4][4][4] = {};
    gemm_main(A + (size_t)bm * EMBED, Bw + (size_t)bn * EMBED, sbase, tid, lane, w, acc);

    int jc = 2 * (lane & 3);
    #pragma unroll
    for (int mt = 0; mt < 4; mt++)
        #pragma unroll
        for (int h = 0; h < 2; h++) {
            int m = bm + wm + mt * 16 + (lane >> 2) + 8 * h;
            int b_ = m >> 11, t_ = m & (SEQ - 1);
            #pragma unroll
            for (int nt = 0; nt < 4; nt++) {
                int n = bn + wn + nt * 8 + jc;
                float2 bv2 = *(const float2*)&bias[n];
                __half2 hv = __floats2half2_rn(acc[mt][nt][2 * h] + bv2.x,
                                               acc[mt][nt][2 * h + 1] + bv2.y);
                int h_ = n >> 6, d_ = n & 63;
                *(__half2*)&Cout[(((size_t)b_ * NHEAD + h_) * SEQ + t_) * HDIM + d_] = hv;
            }
        }
}

// ---------------- output projection: fp32 out ----------------
__global__ __launch_bounds__(256, 2)
void gemm_o(const __half* __restrict__ A, const __half* __restrict__ Bm,
            const float* __restrict__ bias, float* __restrict__ Cout)
{
    extern __shared__ __half sh[];
    uint32_t sbase = smem_u32(sh);
    int tid = threadIdx.x, lane = tid & 31, w = tid >> 5;
    int wm = (w >> 2) * 64, wn = (w & 3) * 32;
    int bm = blockIdx.y * 128, bn = blockIdx.x * 128;

    float acc[4][4][4] = {};
    gemm_main(A + (size_t)bm * EMBED, Bm + (size_t)bn * EMBED, sbase, tid, lane, w, acc);

    int jc = 2 * (lane & 3);
    #pragma unroll
    for (int mt = 0; mt < 4; mt++)
        #pragma unroll
        for (int h = 0; h < 2; h++) {
            int m = bm + wm + mt * 16 + (lane >> 2) + 8 * h;
            #pragma unroll
            for (int nt = 0; nt < 4; nt++) {
                int n = bn + wn + nt * 8 + jc;
                float2 bv2 = *(const float2*)&bias[n];
                float2 v = { acc[mt][nt][2 * h] + bv2.x, acc[mt][nt][2 * h + 1] + bv2.y };
                *(float2*)&Cout[(size_t)m * EMBED + n] = v;
            }
        }
}

// ---------------- fp16 flash attention on compacted keys ----------------
#define SCALE_L2E 0.18033688011112042f   // 0.125 * log2(e)
#define NEGINF2   -1e30f

struct AttnSmemH {
    __half Qs[128 * 72];
    __half Ks[2][64 * 72];    // [key][d]
    __half Vs[2][64 * 72];    // [key][d]
    __half Ps[128 * 72];
};

__global__ __launch_bounds__(256)
void attn_h(const __half* __restrict__ Q, const __half* __restrict__ Kc,
            const __half* __restrict__ Vc, const int* __restrict__ cnt,
            __half* __restrict__ Y)
{
    extern __shared__ char raw[];
    AttnSmemH& sm = *reinterpret_cast<AttnSmemH*>(raw);

    int tid = threadIdx.x, lane = tid & 31, w = tid >> 5;
    int jc = 2 * (lane & 3);
    int bh = blockIdx.y, b = bh >> 4, hh = bh & 15;
    int q0 = blockIdx.x * 128;
    int qb = w * 16;

    int nk = cnt[b];
    int ntiles = (nk + 63) >> 6;

    const __half* Qp = Q  + ((size_t)bh * SEQ + q0) * HDIM;
    const __half* Kp = Kc + (size_t)bh * SEQ * HDIM;
    const __half* Vp = Vc + (size_t)bh * SEQ * HDIM;

    uint32_t uQ = smem_u32(sm.Qs);
    uint32_t uPs = smem_u32(sm.Ps);

    int a_off = (lane & 15) * 144 + (lane >> 4) * 16;
    int b_off = ((lane >> 4) * 8 + (lane & 7)) * 144 + ((lane >> 3) & 1) * 16;

    #pragma unroll
    for (int i = 0; i < 4; i++) {
        int ch = tid + i * 256;
        int r = ch >> 3, c = ch & 7;
        cp16(uQ + r * 144 + c * 16, Qp + (size_t)r * HDIM + c * 8);
    }

    auto prefetch = [&](int ti, int buf) {
        int kt = ti * 64;
        uint32_t uK = smem_u32(sm.Ks[buf]);
        uint32_t uV = smem_u32(sm.Vs[buf]);
        #pragma unroll
        for (int i = 0; i < 2; i++) {
            int ch = tid + i * 256;
            int r = ch >> 3, c = ch & 7;
            cp16(uK + r * 144 + c * 16, Kp + (size_t)(kt + r) * HDIM + c * 8);
            cp16(uV + r * 144 + c * 16, Vp + (size_t)(kt + r) * HDIM + c * 8);
        }
    };

    float o[8][4] = {};
    float mrow[2] = { NEGINF2, NEGINF2 };
    float lrow[2] = { 0.f, 0.f };

    if (ntiles > 0) { prefetch(0, 0); }
    CP_COMMIT();

    for (int ti = 0; ti < ntiles; ti++) {
        int buf = ti & 1;
        CP_WAIT(0);
        __syncthreads();
        if (ti + 1 < ntiles) prefetch(ti + 1, buf ^ 1);
        CP_COMMIT();

        uint32_t uK = smem_u32(sm.Ks[buf]);
        uint32_t uV = smem_u32(sm.Vs[buf]);

        // S = Q K^T
        float s[8][4] = {};
        #pragma unroll
        for (int ks = 0; ks < 4; ks++) {
            uint32_t a0, a1, a2, a3;
            ldsm4(a0, a1, a2, a3, uQ + qb * 144 + ks * 32 + a_off);
            #pragma unroll
            for (int p = 0; p < 4; p++) {
                uint32_t b0a, b1a, b0b, b1b;
                ldsm4(b0a, b1a, b0b, b1b, uK + p * 16 * 144 + ks * 32 + b_off);
                mma16(s[2 * p],     a0, a1, a2, a3, b0a, b1a);
                mma16(s[2 * p + 1], a0, a1, a2, a3, b0b, b1b);
            }
        }

        // scale into log2 domain; tail mask only on last partial tile
        int valid = nk - ti * 64;
        #pragma unroll
        for (int nt = 0; nt < 8; nt++) {
            s[nt][0] *= SCALE_L2E; s[nt][1] *= SCALE_L2E;
            s[nt][2] *= SCALE_L2E; s[nt][3] *= SCALE_L2E;
        }
        if (valid < 64) {
            #pragma unroll
            for (int nt = 0; nt < 8; nt++) {
                int c0 = nt * 8 + jc;
                if (c0 >= valid)     { s[nt][0] = NEGINF2; s[nt][2] = NEGINF2; }
                if (c0 + 1 >= valid) { s[nt][1] = NEGINF2; s[nt][3] = NEGINF2; }
            }
        }

        // online softmax (base-2)
        #pragma unroll
        for (int h = 0; h < 2; h++) {
            float mx = NEGINF2;
            #pragma unroll
            for (int nt = 0; nt < 8; nt++)
                mx = fmaxf(mx, fmaxf(s[nt][2 * h], s[nt][2 * h + 1]));
            mx = fmaxf(mx, __shfl_xor_sync(0xffffffffu, mx, 1));
            mx = fmaxf(mx, __shfl_xor_sync(0xffffffffu, mx, 2));
            float mnew = fmaxf(mrow[h], mx);
            float alpha = ex2f(mrow[h] - mnew);
            mrow[h] = mnew;
            float rs = 0.f;
            #pragma unroll
            for (int nt = 0; nt < 8; nt++) {
                s[nt][2 * h]     = ex2f(s[nt][2 * h]     - mnew);
                s[nt][2 * h + 1] = ex2f(s[nt][2 * h + 1] - mnew);
                rs += s[nt][2 * h] + s[nt][2 * h + 1];
            }
            rs += __shfl_xor_sync(0xffffffffu, rs, 1);
            rs += __shfl_xor_sync(0xffffffffu, rs, 2);
            lrow[h] = lrow[h] * alpha + rs;
            #pragma unroll
            for (int nt = 0; nt < 8; nt++) {
                o[nt][2 * h]     *= alpha;
                o[nt][2 * h + 1] *= alpha;
            }
        }

        // P -> smem (warp-private rows)
        #pragma unroll
        for (int h = 0; h < 2; h++) {
            int pr = (qb + (lane >> 2) + 8 * h) * 72;
            #pragma unroll
            for (int nt = 0; nt < 8; nt++) {
                __half2 hv = __floats2half2_rn(s[nt][2 * h], s[nt][2 * h + 1]);
                *(__half2*)&sm.Ps[pr + nt * 8 + jc] = hv;
            }
        }
        __syncwarp();

        // O += P V  (V row-major [k][d]; B-frags via ldmatrix.trans)
        #pragma unroll
        for (int ks = 0; ks < 4; ks++) {
            uint32_t a0, a1, a2, a3;
            ldsm4(a0, a1, a2, a3, uPs + qb * 144 + ks * 32 + a_off);
            #pragma unroll
            for (int p = 0; p < 4; p++) {
                uint32_t b0a, b1a, b0b, b1b;
                ldsm4t(b0a, b1a, b0b, b1b,
                       uV + (ks * 16 + (lane & 15)) * 144 + p * 32 + (lane >> 4) * 16);
                mma16(o[2 * p],     a0, a1, a2, a3, b0a, b1a);
                mma16(o[2 * p + 1], a0, a1, a2, a3, b0b, b1b);
            }
        }
    }

    // epilogue: normalize, write half [B,T,C]
    #pragma unroll
    for (int h = 0; h < 2; h++) {
        float inv = 1.f / lrow[h];
        int q = q0 + qb + (lane >> 2) + 8 * h;
        #pragma unroll
        for (int nt = 0; nt < 8; nt++) {
            __half2 hv = __floats2half2_rn(o[nt][2 * h] * inv, o[nt][2 * h + 1] * inv);
            *(__half2*)&Y[((size_t)b * SEQ + q) * EMBED + hh * HDIM + nt * 8 + jc] = hv;
        }
    }
}

// ---------------- launch ----------------
extern "C" void kernel_launch(void* const* d_in, const int* in_sizes, int n_in,
                              void* d_out, int out_size)
{
    const float* x    = (const float*)d_in[0];
    const int*   mask = (const int*)  d_in[1];
    const float* Wk   = (const float*)d_in[2];
    const float* bk   = (const float*)d_in[3];
    const float* Wq   = (const float*)d_in[4];
    const float* bq   = (const float*)d_in[5];
    const float* Wv   = (const float*)d_in[6];
    const float* bv   = (const float*)d_in[7];
    const float* Wo   = (const float*)d_in[8];
    const float* bo   = (const float*)d_in[9];
    float* out = (float*)d_out;

    __half *xh, *xc, *wq, *wk, *wv, *wo, *qh, *kc, *vc, *yh;
    int *idx, *cnt;
    cudaGetSymbolAddress((void**)&xh, g_xh);
    cudaGetSymbolAddress((void**)&xc, g_xc);
    cudaGetSymbolAddress((void**)&wq, g_wq);
    cudaGetSymbolAddress((void**)&wk, g_wk);
    cudaGetSymbolAddress((void**)&wv, g_wv);
    cudaGetSymbolAddress((void**)&wo, g_wo);
    cudaGetSymbolAddress((void**)&qh, g_qh);
    cudaGetSymbolAddress((void**)&kc, g_kc);
    cudaGetSymbolAddress((void**)&vc, g_vc);
    cudaGetSymbolAddress((void**)&yh, g_yh);
    cudaGetSymbolAddress((void**)&idx, g_idx);
    cudaGetSymbolAddress((void**)&cnt, g_cnt);

    cudaFuncSetAttribute(gemm_qkv, cudaFuncAttributeMaxDynamicSharedMemorySize, GSMEM);
    cudaFuncSetAttribute(gemm_o,   cudaFuncAttributeMaxDynamicSharedMemorySize, GSMEM);
    cudaFuncSetAttribute(attn_h,   cudaFuncAttributeMaxDynamicSharedMemorySize, (int)sizeof(AttnSmemH));

    compact_idx<<<BATCH, 256>>>(mask, idx, cnt);
    conv_all<<<512, 256>>>((const float4*)x, (const float4*)Wq, (const float4*)Wk,
                           (const float4*)Wv, (const float4*)Wo,
                           (uint2*)xh, (uint2*)wq, (uint2*)wk, (uint2*)wv, (uint2*)wo);

    dim3 ggx(SEQ / 64, BATCH);
    gather_x<<<ggx, 256>>>(xh, xc, idx, cnt);

    dim3 gqkv(EMBED / 128, MROWS / 128, 3);
    gemm_qkv<<<gqkv, 256, GSMEM>>>(xh, xc, wq, wk, wv, bq, bk, bv, qh, kc, vc, cnt);

    dim3 gattn(SEQ / 128, BATCH * NHEAD);
    attn_h<<<gattn, 256, sizeof(AttnSmemH)>>>(qh, kc, vc, cnt, yh);

    dim3 gblk(EMBED / 128, MROWS / 128);
    gemm_o<<<gblk, 256, GSMEM>>>(yh, wo, bo, out);
}